// round 2
// baseline (speedup 1.0000x reference)
#include <cuda_runtime.h>
#include <math.h>

#define BB 256
#define TT 256
#define EE 256
#define HH 1024
#define VV 1024
#define ZDIM 256
#define G3H (3 * HH)
#define NBLK 296

// ---------------- persistent device scratch (no allocation allowed) ----------------
__device__ float g_h0[2][BB][HH];
__device__ float g_h1[2][BB][HH];
__device__ float g_embp[2][BB][EE];
__device__ float g_zemb[BB * EE];
__device__ float g_zh[BB * HH];
__device__ float g_gi0[BB * G3H];
__device__ float g_gh0[BB * G3H];
__device__ float g_gi1[BB * G3H];
__device__ float g_gh1[BB * G3H];

// ---------------- launch-invariant grid barrier ----------------
// g_gen grows monotonically forever (never reset) -> safe across graph replays.
// g_count returns to 0 after every barrier -> state identical at every launch start.
__device__ unsigned g_count = 0;
__device__ unsigned g_gen = 0;

__device__ __forceinline__ void grid_sync() {
    __syncthreads();
    if (threadIdx.x == 0) {
        __threadfence();
        const unsigned snap = atomicAdd(&g_gen, 0u);
        const unsigned my = atomicAdd(&g_count, 1u);
        if (my == (unsigned)(gridDim.x - 1)) {
            atomicExch(&g_count, 0u);
            __threadfence();
            atomicAdd(&g_gen, 1u);
        } else {
            while (atomicAdd(&g_gen, 0u) == snap) { __nanosleep(64); }
        }
        __threadfence();
    }
    __syncthreads();
}

__device__ __forceinline__ float sigmoidf_(float x) { return 1.0f / (1.0f + expf(-x)); }
__device__ __forceinline__ float seluf_(float x) {
    const float sc = 1.0507009873554805f, al = 1.6732632423543772f;
    return x > 0.f ? sc * x : sc * al * expm1f(x);
}

struct GSpec {
    const float* A1; long lda1;   // cols [0, splitK)
    const float* A2; long lda2;   // cols [splitK, K)
    int splitK; int K;
    const float* W;               // (N, K) row-major
    const float* bias;            // (N)
    float* C; long ldc;
    int tilesM; int tilesN;
    int epi;                      // 0 none, 1 selu, 2 relu
};

// ---------------- one 64x64 fp32 tile: C = A @ W^T + bias ----------------
// 256 threads, 4x4 per thread, K-tile 16, double-buffered SMEM. Requires K % 32 == 0
// (even number of 16-K tiles, so the last-used buffer is always buf 1).
__device__ void gemm_tile(const GSpec& s, int m0, int n0,
                          float (*As)[16][72], float (*Ws)[16][72]) {
    const int tid = threadIdx.x;
    const int tx = tid & 15, ty = tid >> 4;
    const int lr = tid >> 2;          // 0..63
    const int lk = (tid & 3) << 2;    // 0,4,8,12
    const int K = s.K, splitK = s.splitK;
    const int nkt = K >> 4;

    const long arow = (long)(m0 + lr);
    const float* Wp = s.W + (long)(n0 + lr) * K + lk;

    float acc[4][4];
#pragma unroll
    for (int i = 0; i < 4; i++)
#pragma unroll
        for (int j = 0; j < 4; j++) acc[i][j] = 0.f;

    float4 a4, w4;
    {
        const int kg = lk;
        const float* p = (kg < splitK) ? (s.A1 + arow * s.lda1 + kg)
                                       : (s.A2 + arow * s.lda2 + (kg - splitK));
        a4 = *(const float4*)p;
        w4 = *(const float4*)Wp;
    }
    As[0][lk + 0][lr] = a4.x; As[0][lk + 1][lr] = a4.y;
    As[0][lk + 2][lr] = a4.z; As[0][lk + 3][lr] = a4.w;
    Ws[0][lk + 0][lr] = w4.x; Ws[0][lk + 1][lr] = w4.y;
    Ws[0][lk + 2][lr] = w4.z; Ws[0][lk + 3][lr] = w4.w;
    __syncthreads();

    for (int kt = 0; kt < nkt; kt++) {
        const int cur = kt & 1;
        const bool more = (kt + 1) < nkt;
        if (more) {
            const int kg = (kt + 1) * 16 + lk;
            const float* p = (kg < splitK) ? (s.A1 + arow * s.lda1 + kg)
                                           : (s.A2 + arow * s.lda2 + (kg - splitK));
            a4 = *(const float4*)p;
            w4 = *(const float4*)(Wp + (kt + 1) * 16);
        }
#pragma unroll
        for (int kk = 0; kk < 16; kk++) {
            const float4 av = *(const float4*)&As[cur][kk][ty << 2];
            const float4 wv = *(const float4*)&Ws[cur][kk][tx << 2];
            acc[0][0] += av.x * wv.x; acc[0][1] += av.x * wv.y;
            acc[0][2] += av.x * wv.z; acc[0][3] += av.x * wv.w;
            acc[1][0] += av.y * wv.x; acc[1][1] += av.y * wv.y;
            acc[1][2] += av.y * wv.z; acc[1][3] += av.y * wv.w;
            acc[2][0] += av.z * wv.x; acc[2][1] += av.z * wv.y;
            acc[2][2] += av.z * wv.z; acc[2][3] += av.z * wv.w;
            acc[3][0] += av.w * wv.x; acc[3][1] += av.w * wv.y;
            acc[3][2] += av.w * wv.z; acc[3][3] += av.w * wv.w;
        }
        if (more) {
            const int nxt = cur ^ 1;
            As[nxt][lk + 0][lr] = a4.x; As[nxt][lk + 1][lr] = a4.y;
            As[nxt][lk + 2][lr] = a4.z; As[nxt][lk + 3][lr] = a4.w;
            Ws[nxt][lk + 0][lr] = w4.x; Ws[nxt][lk + 1][lr] = w4.y;
            Ws[nxt][lk + 2][lr] = w4.z; Ws[nxt][lk + 3][lr] = w4.w;
            __syncthreads();
        }
    }

    const int n = n0 + (tx << 2);
    const float4 bv = *(const float4*)(s.bias + n);
#pragma unroll
    for (int i = 0; i < 4; i++) {
        const int m = m0 + (ty << 2) + i;
        float4 v;
        v.x = acc[i][0] + bv.x; v.y = acc[i][1] + bv.y;
        v.z = acc[i][2] + bv.z; v.w = acc[i][3] + bv.w;
        if (s.epi == 1) { v.x = seluf_(v.x); v.y = seluf_(v.y); v.z = seluf_(v.z); v.w = seluf_(v.w); }
        else if (s.epi == 2) {
            v.x = fmaxf(v.x, 0.f); v.y = fmaxf(v.y, 0.f);
            v.z = fmaxf(v.z, 0.f); v.w = fmaxf(v.w, 0.f);
        }
        *(float4*)(s.C + (long)m * s.ldc + n) = v;
    }
}

__device__ void run_gemm(const GSpec& s, float (*As)[16][72], float (*Ws)[16][72]) {
    const int total = s.tilesM * s.tilesN;
    for (int tile = blockIdx.x; tile < total; tile += gridDim.x)
        gemm_tile(s, (tile / s.tilesN) << 6, (tile % s.tilesN) << 6, As, Ws);
}

__device__ void run_gemm2(const GSpec& sa, const GSpec& sb,
                          float (*As)[16][72], float (*Ws)[16][72]) {
    const int ta = sa.tilesM * sa.tilesN;
    const int tb = sb.tilesM * sb.tilesN;
    for (int tile = blockIdx.x; tile < ta + tb; tile += gridDim.x) {
        if (tile < ta)
            gemm_tile(sa, (tile / sa.tilesN) << 6, (tile % sa.tilesN) << 6, As, Ws);
        else {
            const int u = tile - ta;
            gemm_tile(sb, (u / sb.tilesN) << 6, (u % sb.tilesN) << 6, As, Ws);
        }
    }
}

__device__ void combine_phase(const float* __restrict__ gi, const float* __restrict__ gh,
                              const float* __restrict__ hp, float* __restrict__ hn) {
    for (int i = blockIdx.x * blockDim.x + threadIdx.x; i < BB * HH;
         i += gridDim.x * blockDim.x) {
        const int b = i >> 10;
        const int j = i & (HH - 1);
        const long base = (long)b * G3H;
        const float ir = gi[base + j], iz = gi[base + HH + j], in_ = gi[base + 2 * HH + j];
        const float hr = gh[base + j], hz = gh[base + HH + j], hn_ = gh[base + 2 * HH + j];
        const float r = sigmoidf_(ir + hr);
        const float zg = sigmoidf_(iz + hz);
        const float n = tanhf(in_ + r * hn_);
        hn[(long)b * HH + j] = (1.0f - zg) * n + zg * hp[(long)b * HH + j];
    }
}

__device__ void argmax_phase(const float* __restrict__ probs, long ldp,
                             const float* __restrict__ emb, float* __restrict__ embw,
                             float* __restrict__ samples, int t) {
    __shared__ float sv[256];
    __shared__ int si[256];
    const int tid = threadIdx.x;
    for (int b = blockIdx.x; b < BB; b += gridDim.x) {
        const float* row = probs + (long)b * ldp;
        float best = -1e30f; int bidx = VV;
        for (int j = tid; j < VV; j += 256) {   // ascending -> first max kept per thread
            const float v = row[j];
            if (v > best) { best = v; bidx = j; }
        }
        sv[tid] = best; si[tid] = bidx;
        __syncthreads();
        for (int s = 128; s > 0; s >>= 1) {
            if (tid < s) {
                const float v2 = sv[tid + s]; const int i2 = si[tid + s];
                if (v2 > sv[tid] || (v2 == sv[tid] && i2 < si[tid])) { sv[tid] = v2; si[tid] = i2; }
            }
            __syncthreads();
        }
        const int idx = si[0];
        __syncthreads();
        for (int j = tid; j < EE; j += 256)
            embw[(long)b * EE + j] = emb[(long)idx * EE + j];
        if (tid == 0 && samples) samples[(long)b * TT + t] = (float)idx;
    }
}

// ---------------- the whole decoder as ONE persistent kernel ----------------
__global__ void __launch_bounds__(256, 2) srdecoder_persistent(
    const float* z, const float* emb, const float* x0,
    const float* w_z1, const float* b_z1, const float* w_z2, const float* b_z2,
    const float* w_ih0, const float* w_hh0, const float* b_ih0, const float* b_hh0,
    const float* w_ih1, const float* w_hh1, const float* b_ih1, const float* b_hh1,
    const float* w_out, const float* b_out,
    float* out, float* samples) {

    __shared__ float As[2][16][72];
    __shared__ float Ws[2][16][72];

    // ---- init recurrent state + zh = selu(z @ w_z1^T + b_z1) ----
    for (int i = blockIdx.x * blockDim.x + threadIdx.x; i < BB * HH;
         i += gridDim.x * blockDim.x) {
        ((float*)g_h0)[i] = 0.f;   // slot 0 of g_h0
        ((float*)g_h1)[i] = 0.f;   // slot 0 of g_h1
        if (i < BB * EE) ((float*)g_embp)[i] = x0[i & (EE - 1)];   // slot 0 of g_embp
    }
    {
        GSpec s = { z, ZDIM, z, ZDIM, ZDIM, ZDIM, w_z1, b_z1, g_zh, HH,
                    BB / 64, HH / 64, 1 };
        run_gemm(s, As, Ws);
    }
    grid_sync();

    // ---- z_emb = zh @ w_z2^T + b_z2 ----
    {
        GSpec s = { g_zh, HH, g_zh, HH, HH, HH, w_z2, b_z2, g_zemb, EE,
                    BB / 64, EE / 64, 0 };
        run_gemm(s, As, Ws);
    }
    grid_sync();

    for (int t = 0; t < TT; t++) {
        const int r = t & 1, w = r ^ 1;
        float* h0r = &g_h0[r][0][0]; float* h0w = &g_h0[w][0][0];
        float* h1r = &g_h1[r][0][0]; float* h1w = &g_h1[w][0][0];
        float* er  = &g_embp[r][0][0]; float* ew = &g_embp[w][0][0];

        // layer 0 gates
        {
            GSpec gi = { er, EE, g_zemb, EE, EE, 2 * EE, w_ih0, b_ih0, g_gi0, G3H,
                         BB / 64, G3H / 64, 0 };
            GSpec gh = { h0r, HH, h0r, HH, HH, HH, w_hh0, b_hh0, g_gh0, G3H,
                         BB / 64, G3H / 64, 0 };
            run_gemm2(gi, gh, As, Ws);
        }
        grid_sync();
        combine_phase(g_gi0, g_gh0, h0r, h0w);
        grid_sync();

        // layer 1 gates
        {
            GSpec gi = { h0w, HH, h0w, HH, HH, HH, w_ih1, b_ih1, g_gi1, G3H,
                         BB / 64, G3H / 64, 0 };
            GSpec gh = { h1r, HH, h1r, HH, HH, HH, w_hh1, b_hh1, g_gh1, G3H,
                         BB / 64, G3H / 64, 0 };
            run_gemm2(gi, gh, As, Ws);
        }
        grid_sync();
        combine_phase(g_gi1, g_gh1, h1r, h1w);
        grid_sync();

        // probs = relu(h1_new @ w_out^T + b_out) -> out[b, t, :]
        {
            GSpec s = { h1w, HH, h1w, HH, HH, HH, w_out, b_out,
                        out + (long)t * VV, (long)TT * VV, BB / 64, VV / 64, 2 };
            run_gemm(s, As, Ws);
        }
        grid_sync();

        // argmax + embedding gather + samples
        argmax_phase(out + (long)t * VV, (long)TT * VV, emb, ew, samples, t);
        grid_sync();
    }
}

extern "C" void kernel_launch(void* const* d_in, const int* in_sizes, int n_in,
                              void* d_out, int out_size) {
    const float* z     = (const float*)d_in[0];
    const float* emb   = (const float*)d_in[3];
    const float* x0    = (const float*)d_in[4];
    const float* w_z1  = (const float*)d_in[5];
    const float* b_z1  = (const float*)d_in[6];
    const float* w_z2  = (const float*)d_in[7];
    const float* b_z2  = (const float*)d_in[8];
    const float* w_ih0 = (const float*)d_in[9];
    const float* w_hh0 = (const float*)d_in[10];
    const float* b_ih0 = (const float*)d_in[11];
    const float* b_hh0 = (const float*)d_in[12];
    const float* w_ih1 = (const float*)d_in[13];
    const float* w_hh1 = (const float*)d_in[14];
    const float* b_ih1 = (const float*)d_in[15];
    const float* b_hh1 = (const float*)d_in[16];
    const float* w_out = (const float*)d_in[17];
    const float* b_out = (const float*)d_in[18];
    float* out = (float*)d_out;

    const long BTV = (long)BB * TT * VV;
    float* samples_base = ((long)out_size >= BTV + (long)BB * TT) ? (out + BTV) : nullptr;

    srdecoder_persistent<<<NBLK, 256>>>(
        z, emb, x0, w_z1, b_z1, w_z2, b_z2,
        w_ih0, w_hh0, b_ih0, b_hh0, w_ih1, w_hh1, b_ih1, b_hh1,
        w_out, b_out, out, samples_base);
}

// round 3
// speedup vs baseline: 1.6025x; 1.6025x over previous
#include <cuda_runtime.h>
#include <math.h>

#define BB 256
#define TT 256
#define EE 256
#define HH 1024
#define VV 1024
#define ZDIM 256
#define G3H (3 * HH)
#define NBLK 296

// ---------------- persistent device scratch (no allocation allowed) ----------------
__device__ float g_h0[2][BB][HH];
__device__ float g_h1[2][BB][HH];
__device__ float g_embp[2][BB][EE];
__device__ float g_zemb[BB * EE];
__device__ float g_zh[BB * HH];
__device__ float g_gi0[BB * G3H];
__device__ float g_gh0[BB * G3H];
__device__ float g_gi1[BB * G3H];
__device__ float g_gh1[BB * G3H];

// ---------------- launch-invariant grid barrier ----------------
// g_gen grows monotonically forever (never reset) -> safe across graph replays.
// g_count returns to 0 after every barrier -> state identical at every launch start.
__device__ unsigned g_count = 0;
__device__ unsigned g_gen = 0;

__device__ __forceinline__ void grid_sync() {
    __syncthreads();
    if (threadIdx.x == 0) {
        __threadfence();
        const unsigned snap = atomicAdd(&g_gen, 0u);
        const unsigned my = atomicAdd(&g_count, 1u);
        if (my == (unsigned)(gridDim.x - 1)) {
            atomicExch(&g_count, 0u);
            __threadfence();
            atomicAdd(&g_gen, 1u);
        } else {
            while (atomicAdd(&g_gen, 0u) == snap) { __nanosleep(64); }
        }
        __threadfence();
    }
    __syncthreads();
}

__device__ __forceinline__ float sigmoidf_(float x) { return 1.0f / (1.0f + expf(-x)); }
__device__ __forceinline__ float seluf_(float x) {
    const float sc = 1.0507009873554805f, al = 1.6732632423543772f;
    return x > 0.f ? sc * x : sc * al * expm1f(x);
}

struct GSpec {
    const float* A1; long lda1;   // cols [0, splitK)
    const float* A2; long lda2;   // cols [splitK, K)
    int splitK; int K;
    const float* W;               // (N, K) row-major
    const float* bias;            // (N)
    float* C; long ldc;
    int tilesM; int tilesN;
    int epi;                      // 0 none, 1 selu, 2 relu
};

// ---------------- one 64x64 fp32 tile: C = A @ W^T + bias ----------------
// 256 threads, 4x4 per thread, K-tile 16, double-buffered SMEM. Requires K % 32 == 0
// (even number of 16-K tiles, so the last-used buffer is always buf 1).
__device__ void gemm_tile(const GSpec& s, int m0, int n0,
                          float (*As)[16][72], float (*Ws)[16][72]) {
    const int tid = threadIdx.x;
    const int tx = tid & 15, ty = tid >> 4;
    const int lr = tid >> 2;          // 0..63
    const int lk = (tid & 3) << 2;    // 0,4,8,12
    const int K = s.K, splitK = s.splitK;
    const int nkt = K >> 4;

    const long arow = (long)(m0 + lr);
    const float* Wp = s.W + (long)(n0 + lr) * K + lk;

    float acc[4][4];
#pragma unroll
    for (int i = 0; i < 4; i++)
#pragma unroll
        for (int j = 0; j < 4; j++) acc[i][j] = 0.f;

    float4 a4, w4;
    {
        const int kg = lk;
        const float* p = (kg < splitK) ? (s.A1 + arow * s.lda1 + kg)
                                       : (s.A2 + arow * s.lda2 + (kg - splitK));
        a4 = *(const float4*)p;
        w4 = *(const float4*)Wp;
    }
    As[0][lk + 0][lr] = a4.x; As[0][lk + 1][lr] = a4.y;
    As[0][lk + 2][lr] = a4.z; As[0][lk + 3][lr] = a4.w;
    Ws[0][lk + 0][lr] = w4.x; Ws[0][lk + 1][lr] = w4.y;
    Ws[0][lk + 2][lr] = w4.z; Ws[0][lk + 3][lr] = w4.w;
    __syncthreads();

    for (int kt = 0; kt < nkt; kt++) {
        const int cur = kt & 1;
        const bool more = (kt + 1) < nkt;
        if (more) {
            const int kg = (kt + 1) * 16 + lk;
            const float* p = (kg < splitK) ? (s.A1 + arow * s.lda1 + kg)
                                           : (s.A2 + arow * s.lda2 + (kg - splitK));
            a4 = *(const float4*)p;
            w4 = *(const float4*)(Wp + (kt + 1) * 16);
        }
#pragma unroll
        for (int kk = 0; kk < 16; kk++) {
            const float4 av = *(const float4*)&As[cur][kk][ty << 2];
            const float4 wv = *(const float4*)&Ws[cur][kk][tx << 2];
            acc[0][0] += av.x * wv.x; acc[0][1] += av.x * wv.y;
            acc[0][2] += av.x * wv.z; acc[0][3] += av.x * wv.w;
            acc[1][0] += av.y * wv.x; acc[1][1] += av.y * wv.y;
            acc[1][2] += av.y * wv.z; acc[1][3] += av.y * wv.w;
            acc[2][0] += av.z * wv.x; acc[2][1] += av.z * wv.y;
            acc[2][2] += av.z * wv.z; acc[2][3] += av.z * wv.w;
            acc[3][0] += av.w * wv.x; acc[3][1] += av.w * wv.y;
            acc[3][2] += av.w * wv.z; acc[3][3] += av.w * wv.w;
        }
        if (more) {
            const int nxt = cur ^ 1;
            As[nxt][lk + 0][lr] = a4.x; As[nxt][lk + 1][lr] = a4.y;
            As[nxt][lk + 2][lr] = a4.z; As[nxt][lk + 3][lr] = a4.w;
            Ws[nxt][lk + 0][lr] = w4.x; Ws[nxt][lk + 1][lr] = w4.y;
            Ws[nxt][lk + 2][lr] = w4.z; Ws[nxt][lk + 3][lr] = w4.w;
            __syncthreads();
        }
    }

    const int n = n0 + (tx << 2);
    const float4 bv = *(const float4*)(s.bias + n);
#pragma unroll
    for (int i = 0; i < 4; i++) {
        const int m = m0 + (ty << 2) + i;
        float4 v;
        v.x = acc[i][0] + bv.x; v.y = acc[i][1] + bv.y;
        v.z = acc[i][2] + bv.z; v.w = acc[i][3] + bv.w;
        if (s.epi == 1) { v.x = seluf_(v.x); v.y = seluf_(v.y); v.z = seluf_(v.z); v.w = seluf_(v.w); }
        else if (s.epi == 2) {
            v.x = fmaxf(v.x, 0.f); v.y = fmaxf(v.y, 0.f);
            v.z = fmaxf(v.z, 0.f); v.w = fmaxf(v.w, 0.f);
        }
        *(float4*)(s.C + (long)m * s.ldc + n) = v;
    }
}

__device__ void run_gemm(const GSpec& s, float (*As)[16][72], float (*Ws)[16][72]) {
    const int total = s.tilesM * s.tilesN;
    for (int tile = blockIdx.x; tile < total; tile += gridDim.x)
        gemm_tile(s, (tile / s.tilesN) << 6, (tile % s.tilesN) << 6, As, Ws);
}

__device__ void run_gemm2(const GSpec& sa, const GSpec& sb,
                          float (*As)[16][72], float (*Ws)[16][72]) {
    const int ta = sa.tilesM * sa.tilesN;
    const int tb = sb.tilesM * sb.tilesN;
    for (int tile = blockIdx.x; tile < ta + tb; tile += gridDim.x) {
        if (tile < ta)
            gemm_tile(sa, (tile / sa.tilesN) << 6, (tile % sa.tilesN) << 6, As, Ws);
        else {
            const int u = tile - ta;
            gemm_tile(sb, (u / sb.tilesN) << 6, (u % sb.tilesN) << 6, As, Ws);
        }
    }
}

__device__ void combine_phase(const float* __restrict__ gi, const float* __restrict__ gh,
                              const float* __restrict__ hp, float* __restrict__ hn) {
    for (int i = blockIdx.x * blockDim.x + threadIdx.x; i < BB * HH;
         i += gridDim.x * blockDim.x) {
        const int b = i >> 10;
        const int j = i & (HH - 1);
        const long base = (long)b * G3H;
        const float ir = gi[base + j], iz = gi[base + HH + j], in_ = gi[base + 2 * HH + j];
        const float hr = gh[base + j], hz = gh[base + HH + j], hn_ = gh[base + 2 * HH + j];
        const float r = sigmoidf_(ir + hr);
        const float zg = sigmoidf_(iz + hz);
        const float n = tanhf(in_ + r * hn_);
        hn[(long)b * HH + j] = (1.0f - zg) * n + zg * hp[(long)b * HH + j];
    }
}

__device__ void argmax_phase(const float* __restrict__ probs, long ldp,
                             const float* __restrict__ emb, float* __restrict__ embw,
                             float* __restrict__ samples, int t) {
    __shared__ float sv[256];
    __shared__ int si[256];
    const int tid = threadIdx.x;
    for (int b = blockIdx.x; b < BB; b += gridDim.x) {
        const float* row = probs + (long)b * ldp;
        float best = -1e30f; int bidx = VV;
        for (int j = tid; j < VV; j += 256) {   // ascending -> first max kept per thread
            const float v = row[j];
            if (v > best) { best = v; bidx = j; }
        }
        sv[tid] = best; si[tid] = bidx;
        __syncthreads();
        for (int s = 128; s > 0; s >>= 1) {
            if (tid < s) {
                const float v2 = sv[tid + s]; const int i2 = si[tid + s];
                if (v2 > sv[tid] || (v2 == sv[tid] && i2 < si[tid])) { sv[tid] = v2; si[tid] = i2; }
            }
            __syncthreads();
        }
        const int idx = si[0];
        __syncthreads();
        for (int j = tid; j < EE; j += 256)
            embw[(long)b * EE + j] = emb[(long)idx * EE + j];
        if (tid == 0 && samples) samples[(long)b * TT + t] = (float)idx;
    }
}

// ---------------- the whole decoder as ONE persistent kernel ----------------
__global__ void __launch_bounds__(256, 2) srdecoder_persistent(
    const float* z, const float* emb, const float* x0,
    const float* w_z1, const float* b_z1, const float* w_z2, const float* b_z2,
    const float* w_ih0, const float* w_hh0, const float* b_ih0, const float* b_hh0,
    const float* w_ih1, const float* w_hh1, const float* b_ih1, const float* b_hh1,
    const float* w_out, const float* b_out,
    float* out, float* samples) {

    __shared__ float As[2][16][72];
    __shared__ float Ws[2][16][72];

    // ---- init recurrent state + zh = selu(z @ w_z1^T + b_z1) ----
    for (int i = blockIdx.x * blockDim.x + threadIdx.x; i < BB * HH;
         i += gridDim.x * blockDim.x) {
        ((float*)g_h0)[i] = 0.f;   // slot 0 of g_h0
        ((float*)g_h1)[i] = 0.f;   // slot 0 of g_h1
        if (i < BB * EE) ((float*)g_embp)[i] = x0[i & (EE - 1)];   // slot 0 of g_embp
    }
    {
        GSpec s = { z, ZDIM, z, ZDIM, ZDIM, ZDIM, w_z1, b_z1, g_zh, HH,
                    BB / 64, HH / 64, 1 };
        run_gemm(s, As, Ws);
    }
    grid_sync();

    // ---- z_emb = zh @ w_z2^T + b_z2 ----
    {
        GSpec s = { g_zh, HH, g_zh, HH, HH, HH, w_z2, b_z2, g_zemb, EE,
                    BB / 64, EE / 64, 0 };
        run_gemm(s, As, Ws);
    }
    grid_sync();

    for (int t = 0; t < TT; t++) {
        const int r = t & 1, w = r ^ 1;
        float* h0r = &g_h0[r][0][0]; float* h0w = &g_h0[w][0][0];
        float* h1r = &g_h1[r][0][0]; float* h1w = &g_h1[w][0][0];
        float* er  = &g_embp[r][0][0]; float* ew = &g_embp[w][0][0];

        // layer 0 gates
        {
            GSpec gi = { er, EE, g_zemb, EE, EE, 2 * EE, w_ih0, b_ih0, g_gi0, G3H,
                         BB / 64, G3H / 64, 0 };
            GSpec gh = { h0r, HH, h0r, HH, HH, HH, w_hh0, b_hh0, g_gh0, G3H,
                         BB / 64, G3H / 64, 0 };
            run_gemm2(gi, gh, As, Ws);
        }
        grid_sync();
        combine_phase(g_gi0, g_gh0, h0r, h0w);
        grid_sync();

        // layer 1 gates
        {
            GSpec gi = { h0w, HH, h0w, HH, HH, HH, w_ih1, b_ih1, g_gi1, G3H,
                         BB / 64, G3H / 64, 0 };
            GSpec gh = { h1r, HH, h1r, HH, HH, HH, w_hh1, b_hh1, g_gh1, G3H,
                         BB / 64, G3H / 64, 0 };
            run_gemm2(gi, gh, As, Ws);
        }
        grid_sync();
        combine_phase(g_gi1, g_gh1, h1r, h1w);
        grid_sync();

        // probs = relu(h1_new @ w_out^T + b_out) -> out[b, t, :]
        {
            GSpec s = { h1w, HH, h1w, HH, HH, HH, w_out, b_out,
                        out + (long)t * VV, (long)TT * VV, BB / 64, VV / 64, 2 };
            run_gemm(s, As, Ws);
        }
        grid_sync();

        // argmax + embedding gather + samples
        argmax_phase(out + (long)t * VV, (long)TT * VV, emb, ew, samples, t);
        grid_sync();
    }
}

extern "C" void kernel_launch(void* const* d_in, const int* in_sizes, int n_in,
                              void* d_out, int out_size) {
    const float* z     = (const float*)d_in[0];
    const float* emb   = (const float*)d_in[3];
    const float* x0    = (const float*)d_in[4];
    const float* w_z1  = (const float*)d_in[5];
    const float* b_z1  = (const float*)d_in[6];
    const float* w_z2  = (const float*)d_in[7];
    const float* b_z2  = (const float*)d_in[8];
    const float* w_ih0 = (const float*)d_in[9];
    const float* w_hh0 = (const float*)d_in[10];
    const float* b_ih0 = (const float*)d_in[11];
    const float* b_hh0 = (const float*)d_in[12];
    const float* w_ih1 = (const float*)d_in[13];
    const float* w_hh1 = (const float*)d_in[14];
    const float* b_ih1 = (const float*)d_in[15];
    const float* b_hh1 = (const float*)d_in[16];
    const float* w_out = (const float*)d_in[17];
    const float* b_out = (const float*)d_in[18];
    float* out = (float*)d_out;

    const long BTV = (long)BB * TT * VV;
    float* samples_base = ((long)out_size >= BTV + (long)BB * TT) ? (out + BTV) : nullptr;

    srdecoder_persistent<<<NBLK, 256>>>(
        z, emb, x0, w_z1, b_z1, w_z2, b_z2,
        w_ih0, w_hh0, b_ih0, b_hh0, w_ih1, w_hh1, b_ih1, b_hh1,
        w_out, b_out, out, samples_base);
}

// round 4
// speedup vs baseline: 1.6048x; 1.0014x over previous
#include <cuda_runtime.h>
#include <math.h>

#define BB 256
#define TT 256
#define EE 256
#define HH 1024
#define VV 1024
#define ZDIM 256
#define G3H (3 * HH)
#define NBLK 296

// ---------------- persistent device scratch (no allocation allowed) ----------------
__device__ float g_h0[2][BB][HH];
__device__ float g_h1[2][BB][HH];
__device__ float g_embp[2][BB][EE];
__device__ float g_zemb[BB * EE];
__device__ float g_zh[BB * HH];
__device__ float g_gi0[BB * G3H];
__device__ float g_gh0[BB * G3H];
__device__ float g_gi1[BB * G3H];
__device__ float g_gh1[BB * G3H];

// ---------------- launch-invariant grid barrier ----------------
// g_gen grows monotonically forever (never reset) -> safe across graph replays.
// g_count returns to 0 after every barrier -> state identical at every launch start.
__device__ unsigned g_count = 0;
__device__ unsigned g_gen = 0;

__device__ __forceinline__ void grid_sync() {
    __syncthreads();
    if (threadIdx.x == 0) {
        __threadfence();
        const unsigned snap = atomicAdd(&g_gen, 0u);
        const unsigned my = atomicAdd(&g_count, 1u);
        if (my == (unsigned)(gridDim.x - 1)) {
            atomicExch(&g_count, 0u);
            __threadfence();
            atomicAdd(&g_gen, 1u);
        } else {
            while (atomicAdd(&g_gen, 0u) == snap) { __nanosleep(64); }
        }
        __threadfence();
    }
    __syncthreads();
}

__device__ __forceinline__ float sigmoidf_(float x) { return 1.0f / (1.0f + expf(-x)); }
__device__ __forceinline__ float seluf_(float x) {
    const float sc = 1.0507009873554805f, al = 1.6732632423543772f;
    return x > 0.f ? sc * x : sc * al * expm1f(x);
}

struct GSpec {
    const float* A1; long lda1;   // cols [0, splitK)
    const float* A2; long lda2;   // cols [splitK, K)
    int splitK; int K;
    const float* W;               // (N, K) row-major
    const float* bias;            // (N)
    float* C; long ldc;
    int tilesM; int tilesN;
    int epi;                      // 0 none, 1 selu, 2 relu
};

// ---------------- one 64x64 fp32 tile: C = A @ W^T + bias ----------------
// 256 threads, 4x4 per thread, K-tile 16, double-buffered SMEM. Requires K % 32 == 0
// (even number of 16-K tiles, so the last-used buffer is always buf 1).
__device__ void gemm_tile(const GSpec& s, int m0, int n0,
                          float (*As)[16][72], float (*Ws)[16][72]) {
    const int tid = threadIdx.x;
    const int tx = tid & 15, ty = tid >> 4;
    const int lr = tid >> 2;          // 0..63
    const int lk = (tid & 3) << 2;    // 0,4,8,12
    const int K = s.K, splitK = s.splitK;
    const int nkt = K >> 4;

    const long arow = (long)(m0 + lr);
    const float* Wp = s.W + (long)(n0 + lr) * K + lk;

    float acc[4][4];
#pragma unroll
    for (int i = 0; i < 4; i++)
#pragma unroll
        for (int j = 0; j < 4; j++) acc[i][j] = 0.f;

    float4 a4, w4;
    {
        const int kg = lk;
        const float* p = (kg < splitK) ? (s.A1 + arow * s.lda1 + kg)
                                       : (s.A2 + arow * s.lda2 + (kg - splitK));
        a4 = *(const float4*)p;
        w4 = *(const float4*)Wp;
    }
    As[0][lk + 0][lr] = a4.x; As[0][lk + 1][lr] = a4.y;
    As[0][lk + 2][lr] = a4.z; As[0][lk + 3][lr] = a4.w;
    Ws[0][lk + 0][lr] = w4.x; Ws[0][lk + 1][lr] = w4.y;
    Ws[0][lk + 2][lr] = w4.z; Ws[0][lk + 3][lr] = w4.w;
    __syncthreads();

    for (int kt = 0; kt < nkt; kt++) {
        const int cur = kt & 1;
        const bool more = (kt + 1) < nkt;
        if (more) {
            const int kg = (kt + 1) * 16 + lk;
            const float* p = (kg < splitK) ? (s.A1 + arow * s.lda1 + kg)
                                           : (s.A2 + arow * s.lda2 + (kg - splitK));
            a4 = *(const float4*)p;
            w4 = *(const float4*)(Wp + (kt + 1) * 16);
        }
#pragma unroll
        for (int kk = 0; kk < 16; kk++) {
            const float4 av = *(const float4*)&As[cur][kk][ty << 2];
            const float4 wv = *(const float4*)&Ws[cur][kk][tx << 2];
            acc[0][0] += av.x * wv.x; acc[0][1] += av.x * wv.y;
            acc[0][2] += av.x * wv.z; acc[0][3] += av.x * wv.w;
            acc[1][0] += av.y * wv.x; acc[1][1] += av.y * wv.y;
            acc[1][2] += av.y * wv.z; acc[1][3] += av.y * wv.w;
            acc[2][0] += av.z * wv.x; acc[2][1] += av.z * wv.y;
            acc[2][2] += av.z * wv.z; acc[2][3] += av.z * wv.w;
            acc[3][0] += av.w * wv.x; acc[3][1] += av.w * wv.y;
            acc[3][2] += av.w * wv.z; acc[3][3] += av.w * wv.w;
        }
        if (more) {
            const int nxt = cur ^ 1;
            As[nxt][lk + 0][lr] = a4.x; As[nxt][lk + 1][lr] = a4.y;
            As[nxt][lk + 2][lr] = a4.z; As[nxt][lk + 3][lr] = a4.w;
            Ws[nxt][lk + 0][lr] = w4.x; Ws[nxt][lk + 1][lr] = w4.y;
            Ws[nxt][lk + 2][lr] = w4.z; Ws[nxt][lk + 3][lr] = w4.w;
            __syncthreads();
        }
    }

    const int n = n0 + (tx << 2);
    const float4 bv = *(const float4*)(s.bias + n);
#pragma unroll
    for (int i = 0; i < 4; i++) {
        const int m = m0 + (ty << 2) + i;
        float4 v;
        v.x = acc[i][0] + bv.x; v.y = acc[i][1] + bv.y;
        v.z = acc[i][2] + bv.z; v.w = acc[i][3] + bv.w;
        if (s.epi == 1) { v.x = seluf_(v.x); v.y = seluf_(v.y); v.z = seluf_(v.z); v.w = seluf_(v.w); }
        else if (s.epi == 2) {
            v.x = fmaxf(v.x, 0.f); v.y = fmaxf(v.y, 0.f);
            v.z = fmaxf(v.z, 0.f); v.w = fmaxf(v.w, 0.f);
        }
        *(float4*)(s.C + (long)m * s.ldc + n) = v;
    }
}

__device__ void run_gemm(const GSpec& s, float (*As)[16][72], float (*Ws)[16][72]) {
    const int total = s.tilesM * s.tilesN;
    for (int tile = blockIdx.x; tile < total; tile += gridDim.x)
        gemm_tile(s, (tile / s.tilesN) << 6, (tile % s.tilesN) << 6, As, Ws);
}

__device__ void run_gemm2(const GSpec& sa, const GSpec& sb,
                          float (*As)[16][72], float (*Ws)[16][72]) {
    const int ta = sa.tilesM * sa.tilesN;
    const int tb = sb.tilesM * sb.tilesN;
    for (int tile = blockIdx.x; tile < ta + tb; tile += gridDim.x) {
        if (tile < ta)
            gemm_tile(sa, (tile / sa.tilesN) << 6, (tile % sa.tilesN) << 6, As, Ws);
        else {
            const int u = tile - ta;
            gemm_tile(sb, (u / sb.tilesN) << 6, (u % sb.tilesN) << 6, As, Ws);
        }
    }
}

__device__ void combine_phase(const float* __restrict__ gi, const float* __restrict__ gh,
                              const float* __restrict__ hp, float* __restrict__ hn) {
    for (int i = blockIdx.x * blockDim.x + threadIdx.x; i < BB * HH;
         i += gridDim.x * blockDim.x) {
        const int b = i >> 10;
        const int j = i & (HH - 1);
        const long base = (long)b * G3H;
        const float ir = gi[base + j], iz = gi[base + HH + j], in_ = gi[base + 2 * HH + j];
        const float hr = gh[base + j], hz = gh[base + HH + j], hn_ = gh[base + 2 * HH + j];
        const float r = sigmoidf_(ir + hr);
        const float zg = sigmoidf_(iz + hz);
        const float n = tanhf(in_ + r * hn_);
        hn[(long)b * HH + j] = (1.0f - zg) * n + zg * hp[(long)b * HH + j];
    }
}

__device__ void argmax_phase(const float* __restrict__ probs, long ldp,
                             const float* __restrict__ emb, float* __restrict__ embw,
                             float* __restrict__ samples, int t) {
    __shared__ float sv[256];
    __shared__ int si[256];
    const int tid = threadIdx.x;
    for (int b = blockIdx.x; b < BB; b += gridDim.x) {
        const float* row = probs + (long)b * ldp;
        float best = -1e30f; int bidx = VV;
        for (int j = tid; j < VV; j += 256) {   // ascending -> first max kept per thread
            const float v = row[j];
            if (v > best) { best = v; bidx = j; }
        }
        sv[tid] = best; si[tid] = bidx;
        __syncthreads();
        for (int s = 128; s > 0; s >>= 1) {
            if (tid < s) {
                const float v2 = sv[tid + s]; const int i2 = si[tid + s];
                if (v2 > sv[tid] || (v2 == sv[tid] && i2 < si[tid])) { sv[tid] = v2; si[tid] = i2; }
            }
            __syncthreads();
        }
        const int idx = si[0];
        __syncthreads();
        for (int j = tid; j < EE; j += 256)
            embw[(long)b * EE + j] = emb[(long)idx * EE + j];
        if (tid == 0 && samples) samples[(long)b * TT + t] = (float)idx;
    }
}

// ---------------- the whole decoder as ONE persistent kernel ----------------
__global__ void __launch_bounds__(256, 2) srdecoder_persistent(
    const float* z, const float* emb, const float* x0,
    const float* w_z1, const float* b_z1, const float* w_z2, const float* b_z2,
    const float* w_ih0, const float* w_hh0, const float* b_ih0, const float* b_hh0,
    const float* w_ih1, const float* w_hh1, const float* b_ih1, const float* b_hh1,
    const float* w_out, const float* b_out,
    float* out, float* samples) {

    __shared__ float As[2][16][72];
    __shared__ float Ws[2][16][72];

    // ---- init recurrent state + zh = selu(z @ w_z1^T + b_z1) ----
    for (int i = blockIdx.x * blockDim.x + threadIdx.x; i < BB * HH;
         i += gridDim.x * blockDim.x) {
        ((float*)g_h0)[i] = 0.f;   // slot 0 of g_h0
        ((float*)g_h1)[i] = 0.f;   // slot 0 of g_h1
        if (i < BB * EE) ((float*)g_embp)[i] = x0[i & (EE - 1)];   // slot 0 of g_embp
    }
    {
        GSpec s = { z, ZDIM, z, ZDIM, ZDIM, ZDIM, w_z1, b_z1, g_zh, HH,
                    BB / 64, HH / 64, 1 };
        run_gemm(s, As, Ws);
    }
    grid_sync();

    // ---- z_emb = zh @ w_z2^T + b_z2 ----
    {
        GSpec s = { g_zh, HH, g_zh, HH, HH, HH, w_z2, b_z2, g_zemb, EE,
                    BB / 64, EE / 64, 0 };
        run_gemm(s, As, Ws);
    }
    grid_sync();

    for (int t = 0; t < TT; t++) {
        const int r = t & 1, w = r ^ 1;
        float* h0r = &g_h0[r][0][0]; float* h0w = &g_h0[w][0][0];
        float* h1r = &g_h1[r][0][0]; float* h1w = &g_h1[w][0][0];
        float* er  = &g_embp[r][0][0]; float* ew = &g_embp[w][0][0];

        // layer 0 gates
        {
            GSpec gi = { er, EE, g_zemb, EE, EE, 2 * EE, w_ih0, b_ih0, g_gi0, G3H,
                         BB / 64, G3H / 64, 0 };
            GSpec gh = { h0r, HH, h0r, HH, HH, HH, w_hh0, b_hh0, g_gh0, G3H,
                         BB / 64, G3H / 64, 0 };
            run_gemm2(gi, gh, As, Ws);
        }
        grid_sync();
        combine_phase(g_gi0, g_gh0, h0r, h0w);
        grid_sync();

        // layer 1 gates
        {
            GSpec gi = { h0w, HH, h0w, HH, HH, HH, w_ih1, b_ih1, g_gi1, G3H,
                         BB / 64, G3H / 64, 0 };
            GSpec gh = { h1r, HH, h1r, HH, HH, HH, w_hh1, b_hh1, g_gh1, G3H,
                         BB / 64, G3H / 64, 0 };
            run_gemm2(gi, gh, As, Ws);
        }
        grid_sync();
        combine_phase(g_gi1, g_gh1, h1r, h1w);
        grid_sync();

        // probs = relu(h1_new @ w_out^T + b_out) -> out[b, t, :]
        {
            GSpec s = { h1w, HH, h1w, HH, HH, HH, w_out, b_out,
                        out + (long)t * VV, (long)TT * VV, BB / 64, VV / 64, 2 };
            run_gemm(s, As, Ws);
        }
        grid_sync();

        // argmax + embedding gather + samples
        argmax_phase(out + (long)t * VV, (long)TT * VV, emb, ew, samples, t);
        grid_sync();
    }
}

extern "C" void kernel_launch(void* const* d_in, const int* in_sizes, int n_in,
                              void* d_out, int out_size) {
    const float* z     = (const float*)d_in[0];
    const float* emb   = (const float*)d_in[3];
    const float* x0    = (const float*)d_in[4];
    const float* w_z1  = (const float*)d_in[5];
    const float* b_z1  = (const float*)d_in[6];
    const float* w_z2  = (const float*)d_in[7];
    const float* b_z2  = (const float*)d_in[8];
    const float* w_ih0 = (const float*)d_in[9];
    const float* w_hh0 = (const float*)d_in[10];
    const float* b_ih0 = (const float*)d_in[11];
    const float* b_hh0 = (const float*)d_in[12];
    const float* w_ih1 = (const float*)d_in[13];
    const float* w_hh1 = (const float*)d_in[14];
    const float* b_ih1 = (const float*)d_in[15];
    const float* b_hh1 = (const float*)d_in[16];
    const float* w_out = (const float*)d_in[17];
    const float* b_out = (const float*)d_in[18];
    float* out = (float*)d_out;

    const long BTV = (long)BB * TT * VV;
    float* samples_base = ((long)out_size >= BTV + (long)BB * TT) ? (out + BTV) : nullptr;

    srdecoder_persistent<<<NBLK, 256>>>(
        z, emb, x0, w_z1, b_z1, w_z2, b_z2,
        w_ih0, w_hh0, b_ih0, b_hh0, w_ih1, w_hh1, b_ih1, b_hh1,
        w_out, b_out, out, samples_base);
}

// round 7
// speedup vs baseline: 1.6770x; 1.0450x over previous
#include <cuda_runtime.h>
#include <cuda_bf16.h>
#include <math.h>
#include <stdint.h>

#define BB 256
#define TT 256
#define HH 1024
#define VV 1024
#define G3H 3072
#define NBLK 148
#define BH (BB * HH)

// ---------------- persistent device state ----------------
__device__ float g_h0f[2][BH];
__device__ float g_h1f[2][BH];
__device__ float g_pgi0[3L * BB * G3H];
__device__ float g_pgh0[3L * BB * G3H];
__device__ float g_pgi1[3L * BB * G3H];
__device__ float g_pgh1[3L * BB * G3H];
__device__ float g_pout[6L * BB * VV];

__device__ __nv_bfloat16 g_zs[3L * BB * 256];
__device__ __nv_bfloat16 g_zhs[3L * BH];
__device__ __nv_bfloat16 g_xcats[3L * BB * 512];
__device__ __nv_bfloat16 g_h0s[2][3L * BH];
__device__ __nv_bfloat16 g_h1s[2][3L * BH];
__device__ __nv_bfloat16 g_wz1s[3L * HH * 256];
__device__ __nv_bfloat16 g_wz2s[3L * 256 * HH];
__device__ __nv_bfloat16 g_wih0s[3L * G3H * 512];
__device__ __nv_bfloat16 g_whh0s[3L * G3H * HH];
__device__ __nv_bfloat16 g_wih1s[3L * G3H * HH];
__device__ __nv_bfloat16 g_whh1s[3L * G3H * HH];
__device__ __nv_bfloat16 g_wouts[3L * VV * HH];

__constant__ int TA6c[6] = {0, 0, 1, 1, 0, 2};
__constant__ int TB6c[6] = {0, 1, 0, 1, 2, 0};

// ---------------- launch-invariant grid barrier (proven R3) ----------------
__device__ unsigned g_count = 0;
__device__ unsigned g_gen = 0;

__device__ __forceinline__ void grid_sync() {
    __syncthreads();
    if (threadIdx.x == 0) {
        __threadfence();
        const unsigned snap = atomicAdd(&g_gen, 0u);
        const unsigned my = atomicAdd(&g_count, 1u);
        if (my == (unsigned)(gridDim.x - 1)) {
            atomicExch(&g_count, 0u);
            __threadfence();
            atomicAdd(&g_gen, 1u);
        } else {
            while (atomicAdd(&g_gen, 0u) == snap) { __nanosleep(64); }
        }
        __threadfence();
    }
    __syncthreads();
}

// ---------------- small helpers ----------------
__device__ __forceinline__ uint32_t smem_u32(const void* p) {
    uint32_t a;
    asm("{ .reg .u64 t; cvta.to.shared.u64 t, %1; cvt.u32.u64 %0, t; }" : "=r"(a) : "l"(p));
    return a;
}
#define STS128X(r0, r1, r2, r3, a) \
    asm volatile("st.shared.v4.b32 [%0], {%1, %2, %3, %4};" :: "r"(a), "r"(r0), "r"(r1), "r"(r2), "r"(r3) : "memory")

__device__ __forceinline__ void ldm4(uint32_t* r, uint32_t a) {
    asm volatile("ldmatrix.sync.aligned.m8n8.x4.shared.b16 {%0,%1,%2,%3}, [%4];"
                 : "=r"(r[0]), "=r"(r[1]), "=r"(r[2]), "=r"(r[3]) : "r"(a));
}
__device__ __forceinline__ void mma16816(float* c, const uint32_t* a, const uint32_t* b) {
    asm volatile(
        "mma.sync.aligned.m16n8k16.row.col.f32.bf16.bf16.f32 "
        "{%0,%1,%2,%3}, {%4,%5,%6,%7}, {%8,%9}, {%0,%1,%2,%3};"
        : "+f"(c[0]), "+f"(c[1]), "+f"(c[2]), "+f"(c[3])
        : "r"(a[0]), "r"(a[1]), "r"(a[2]), "r"(a[3]), "r"(b[0]), "r"(b[1]));
}

__device__ __forceinline__ float sigmoidf_(float x) { return 1.0f / (1.0f + expf(-x)); }
__device__ __forceinline__ float seluf_(float x) {
    const float sc = 1.0507009873554805f, al = 1.6732632423543772f;
    return x > 0.f ? sc * x : sc * al * expm1f(x);
}
__device__ __forceinline__ void split3(float a, __nv_bfloat16& o0, __nv_bfloat16& o1,
                                       __nv_bfloat16& o2) {
    o0 = __float2bfloat16_rn(a);
    float r = a - __bfloat162float(o0);
    o1 = __float2bfloat16_rn(r);
    r -= __bfloat162float(o1);
    o2 = __float2bfloat16_rn(r);
}

// ---------------- HMMA unit: 128x128 tile, terms [slice*tps, +tps) ----------------
struct MG {
    const __nv_bfloat16* A; long aps;   // activation planes base / plane stride
    const __nv_bfloat16* W; long wps;   // weight planes base / plane stride
    int K; int k32; int tps; int nSlices; int nTilesN; int N;
    float* P;                            // partial out: + slice*BB*N
};

__device__ void mma_unit(const MG& g, int m0, int n0, int slice,
                         uint32_t sA, uint32_t sW) {
    const int tid = threadIdx.x, lane = tid & 31, wid = tid >> 5;
    const int wm = wid >> 2, wn = wid & 3;

    float acc[4][4][4];
#pragma unroll
    for (int i = 0; i < 4; i++)
#pragma unroll
        for (int j = 0; j < 4; j++)
#pragma unroll
            for (int c = 0; c < 4; c++) acc[i][j][c] = 0.f;

    const int t0 = slice * g.tps;
    const int nit = g.tps * g.k32;
    const int row = tid >> 1;                               // 0..127
    const int cs = (tid & 1) << 4;                          // elem offset 0/16
    const uint32_t soff = (uint32_t)row * 80 + ((tid & 1) << 5);
    const uint32_t aoff =
        (uint32_t)(wm * 64 + ((lane >> 3) & 1) * 8 + (lane & 7)) * 80 + ((lane >> 4) << 4);
    const uint32_t woff =
        (uint32_t)(wn * 32 + ((lane >> 4) << 3) + (lane & 7)) * 80 + (((lane >> 3) & 1) << 4);

    uint4 ra0, ra1, rw0, rw1;
    {   // load iter 0
        const __nv_bfloat16* Ap = g.A + (long)TA6c[t0] * g.aps + (long)(m0 + row) * g.K + cs;
        const __nv_bfloat16* Wp = g.W + (long)TB6c[t0] * g.wps + (long)(n0 + row) * g.K + cs;
        ra0 = ((const uint4*)Ap)[0]; ra1 = ((const uint4*)Ap)[1];
        rw0 = ((const uint4*)Wp)[0]; rw1 = ((const uint4*)Wp)[1];
    }
    {   // store buf 0
        const uint32_t a = sA + soff, w = sW + soff;
        STS128X(ra0.x, ra0.y, ra0.z, ra0.w, a);
        STS128X(ra1.x, ra1.y, ra1.z, ra1.w, a + 16);
        STS128X(rw0.x, rw0.y, rw0.z, rw0.w, w);
        STS128X(rw1.x, rw1.y, rw1.z, rw1.w, w + 16);
    }
    __syncthreads();

    for (int it = 0; it < nit; it++) {
        const int cur = it & 1;
        const bool more = (it + 1) < nit;
        if (more) {
            int tt = it + 1, term = t0;
            if (tt >= g.k32) { tt -= g.k32; term++; }
            const __nv_bfloat16* Ap =
                g.A + (long)TA6c[term] * g.aps + (long)(m0 + row) * g.K + tt * 32 + cs;
            const __nv_bfloat16* Wp =
                g.W + (long)TB6c[term] * g.wps + (long)(n0 + row) * g.K + tt * 32 + cs;
            ra0 = ((const uint4*)Ap)[0]; ra1 = ((const uint4*)Ap)[1];
            rw0 = ((const uint4*)Wp)[0]; rw1 = ((const uint4*)Wp)[1];
        }
        const uint32_t ab = sA + cur * 10240 + aoff;
        const uint32_t wb = sW + cur * 10240 + woff;
#pragma unroll
        for (int s = 0; s < 2; s++) {
            uint32_t af[4][4], b0[4], b1[4];
#pragma unroll
            for (int mt = 0; mt < 4; mt++) ldm4(af[mt], ab + mt * (16 * 80) + s * 32);
            ldm4(b0, wb + s * 32);
            ldm4(b1, wb + 16 * 80 + s * 32);
#pragma unroll
            for (int mt = 0; mt < 4; mt++) {
                mma16816(acc[mt][0], af[mt], b0);
                mma16816(acc[mt][1], af[mt], b0 + 2);
                mma16816(acc[mt][2], af[mt], b1);
                mma16816(acc[mt][3], af[mt], b1 + 2);
            }
        }
        if (more) {
            const uint32_t nb = (cur ^ 1) * 10240;
            const uint32_t a = sA + nb + soff, w = sW + nb + soff;
            STS128X(ra0.x, ra0.y, ra0.z, ra0.w, a);
            STS128X(ra1.x, ra1.y, ra1.z, ra1.w, a + 16);
            STS128X(rw0.x, rw0.y, rw0.z, rw0.w, w);
            STS128X(rw1.x, rw1.y, rw1.z, rw1.w, w + 16);
            __syncthreads();
        }
    }

    float* P = g.P + (long)slice * BB * g.N;
#pragma unroll
    for (int mt = 0; mt < 4; mt++)
#pragma unroll
        for (int nt = 0; nt < 4; nt++) {
            const int m = m0 + wm * 64 + mt * 16 + (lane >> 2);
            const int n = n0 + wn * 32 + nt * 8 + (lane & 3) * 2;
            *(float2*)(P + (long)m * g.N + n) = make_float2(acc[mt][nt][0], acc[mt][nt][1]);
            *(float2*)(P + (long)(m + 8) * g.N + n) = make_float2(acc[mt][nt][2], acc[mt][nt][3]);
        }
    __syncthreads();
}

__device__ void run_units(const MG& ga, const MG* gb, uint32_t sA, uint32_t sW) {
    const int na = 2 * ga.nTilesN * ga.nSlices;
    const int nb = gb ? 2 * gb->nTilesN * gb->nSlices : 0;
    for (int u = blockIdx.x; u < na + nb; u += gridDim.x) {
        const MG& g = (u < na) ? ga : *gb;
        const int v = (u < na) ? u : u - na;
        const int slice = v % g.nSlices;
        const int tile = v / g.nSlices;
        mma_unit(g, (tile / g.nTilesN) * 128, (tile % g.nTilesN) * 128, slice, sA, sW);
    }
}

// ---------------- elementwise phases ----------------
__device__ void split_mat(const float* w, __nv_bfloat16* d, long n) {
    const long st = (long)gridDim.x * blockDim.x;
    for (long i = (long)blockIdx.x * blockDim.x + threadIdx.x; i < n; i += st) {
        __nv_bfloat16 s0, s1, s2; split3(w[i], s0, s1, s2);
        d[i] = s0; d[n + i] = s1; d[2 * n + i] = s2;
    }
}

__device__ void combine_gru(const float* pgi, const float* pgh,
                            const float* bih, const float* bhh,
                            const float* hp, float* hn, __nv_bfloat16* hs) {
    const long S = (long)BB * G3H;
    for (int i = blockIdx.x * blockDim.x + threadIdx.x; i < BH; i += gridDim.x * blockDim.x) {
        const int b = i >> 10, j = i & 1023;
        const long r0 = (long)b * G3H + j, z0 = r0 + HH, n0 = r0 + 2 * HH;
        const float gir = pgi[r0] + pgi[S + r0] + pgi[2 * S + r0] + bih[j];
        const float giz = pgi[z0] + pgi[S + z0] + pgi[2 * S + z0] + bih[HH + j];
        const float gin = pgi[n0] + pgi[S + n0] + pgi[2 * S + n0] + bih[2 * HH + j];
        const float ghr = pgh[r0] + pgh[S + r0] + pgh[2 * S + r0] + bhh[j];
        const float ghz = pgh[z0] + pgh[S + z0] + pgh[2 * S + z0] + bhh[HH + j];
        const float ghn = pgh[n0] + pgh[S + n0] + pgh[2 * S + n0] + bhh[2 * HH + j];
        const float r = sigmoidf_(gir + ghr);
        const float zg = sigmoidf_(giz + ghz);
        const float n = tanhf(gin + r * ghn);
        const float v = (1.0f - zg) * n + zg * hp[i];
        hn[i] = v;
        __nv_bfloat16 s0, s1, s2; split3(v, s0, s1, s2);
        hs[i] = s0; hs[BH + i] = s1; hs[2 * BH + i] = s2;
    }
}

__device__ void argmax_phase(const float* bout, float* out, const float* emb,
                             float* samples, int t, float* sv, int* si) {
    const long S = (long)BB * VV;
    const int tid = threadIdx.x;
    for (int b = blockIdx.x; b < BB; b += gridDim.x) {
        const float* pb = g_pout + (long)b * VV;
        float* orow = out + (long)b * TT * VV + (long)t * VV;
        float best = -1e30f; int bidx = VV;
        for (int j = tid; j < VV; j += 256) {
            float v = pb[j] + pb[S + j] + pb[2 * S + j] + pb[3 * S + j] +
                      pb[4 * S + j] + pb[5 * S + j] + bout[j];
            v = fmaxf(v, 0.f);
            orow[j] = v;
            if (v > best) { best = v; bidx = j; }
        }
        sv[tid] = best; si[tid] = bidx;
        __syncthreads();
        for (int s = 128; s > 0; s >>= 1) {
            if (tid < s) {
                const float v2 = sv[tid + s]; const int i2 = si[tid + s];
                if (v2 > sv[tid] || (v2 == sv[tid] && i2 < si[tid])) { sv[tid] = v2; si[tid] = i2; }
            }
            __syncthreads();
        }
        const int idx = si[0];
        __syncthreads();
        for (int jj = tid; jj < 256; jj += 256) {
            __nv_bfloat16 s0, s1, s2;
            split3(emb[(long)idx * 256 + jj], s0, s1, s2);
            __nv_bfloat16* xc = g_xcats + (long)b * 512 + jj;
            xc[0] = s0; xc[131072] = s1; xc[262144] = s2;
        }
        if (tid == 0 && samples) samples[(long)b * TT + t] = (float)idx;
        __syncthreads();
    }
}

// ---------------- the whole decoder, ONE persistent kernel ----------------
__global__ void __launch_bounds__(256, 1) srdec(
    const float* z, const float* emb, const float* x0,
    const float* w_z1, const float* b_z1, const float* w_z2, const float* b_z2,
    const float* w_ih0, const float* w_hh0, const float* b_ih0, const float* b_hh0,
    const float* w_ih1, const float* w_hh1, const float* b_ih1, const float* b_hh1,
    const float* w_out, const float* b_out, float* out, float* samples) {

    __shared__ __align__(16) uint8_t sAbuf[2][10240];
    __shared__ __align__(16) uint8_t sWbuf[2][10240];
    __shared__ float sv[256];
    __shared__ int si[256];
    const uint32_t sA = smem_u32(&sAbuf[0][0]);
    const uint32_t sW = smem_u32(&sWbuf[0][0]);
    const int tid = threadIdx.x;
    const int gst = gridDim.x * blockDim.x;

    // ---- P1: init state + split weights/z ----
    {
        const __nv_bfloat16 zb = __float2bfloat16(0.f);
        for (int i = blockIdx.x * blockDim.x + tid; i < BH; i += gst) {
            g_h0f[0][i] = 0.f; g_h1f[0][i] = 0.f;
            g_h0s[0][i] = zb; g_h0s[0][BH + i] = zb; g_h0s[0][2 * BH + i] = zb;
            g_h1s[0][i] = zb; g_h1s[0][BH + i] = zb; g_h1s[0][2 * BH + i] = zb;
        }
        for (int i = blockIdx.x * blockDim.x + tid; i < BB * 256; i += gst) {
            const int b = i >> 8, k = i & 255;
            __nv_bfloat16 s0, s1, s2; split3(x0[k], s0, s1, s2);
            __nv_bfloat16* xc = g_xcats + (long)b * 512 + k;
            xc[0] = s0; xc[131072] = s1; xc[262144] = s2;
        }
        split_mat(z, g_zs, (long)BB * 256);
        split_mat(w_z1, g_wz1s, (long)HH * 256);
        split_mat(w_z2, g_wz2s, (long)256 * HH);
        split_mat(w_ih0, g_wih0s, (long)G3H * 512);
        split_mat(w_hh0, g_whh0s, (long)G3H * HH);
        split_mat(w_ih1, g_wih1s, (long)G3H * HH);
        split_mat(w_hh1, g_whh1s, (long)G3H * HH);
        split_mat(w_out, g_wouts, (long)VV * HH);
    }
    grid_sync();

    // ---- P2: zh_raw = z @ w_z1^T (partials) ----
    {
        MG s = { g_zs, (long)BB * 256, g_wz1s, (long)HH * 256,
                 256, 8, 2, 3, 8, 1024, g_pgi0 };
        run_units(s, nullptr, sA, sW);
    }
    grid_sync();
    // ---- P3: zh = selu(sum + b_z1), split ----
    for (int i = blockIdx.x * blockDim.x + tid; i < BH; i += gst) {
        const int j = i & 1023;
        const float v = seluf_(g_pgi0[i] + g_pgi0[BH + i] + g_pgi0[2 * BH + i] + b_z1[j]);
        __nv_bfloat16 s0, s1, s2; split3(v, s0, s1, s2);
        g_zhs[i] = s0; g_zhs[BH + i] = s1; g_zhs[2 * BH + i] = s2;
    }
    grid_sync();
    // ---- P4: zemb = zhs @ w_z2^T (partials) ----
    {
        MG s = { g_zhs, (long)BH, g_wz2s, (long)256 * HH,
                 1024, 32, 2, 3, 2, 256, g_pgi0 };
        run_units(s, nullptr, sA, sW);
    }
    grid_sync();
    // ---- P5: zemb combine -> xcat[:,256:512] ----
    for (int i = blockIdx.x * blockDim.x + tid; i < BB * 256; i += gst) {
        const int b = i >> 8, k = i & 255;
        const float v = g_pgi0[i] + g_pgi0[65536 + i] + g_pgi0[131072 + i] + b_z2[k];
        __nv_bfloat16 s0, s1, s2; split3(v, s0, s1, s2);
        __nv_bfloat16* xc = g_xcats + (long)b * 512 + 256 + k;
        xc[0] = s0; xc[131072] = s1; xc[262144] = s2;
    }
    grid_sync();

    for (int t = 0; t < TT; t++) {
        const int r = t & 1, w = r ^ 1;

        {   // layer 0 gates
            MG gi = { g_xcats, 131072L, g_wih0s, (long)G3H * 512,
                      512, 16, 2, 3, 24, G3H, g_pgi0 };
            MG gh = { g_h0s[r], (long)BH, g_whh0s, (long)G3H * HH,
                      1024, 32, 2, 3, 24, G3H, g_pgh0 };
            run_units(gi, &gh, sA, sW);
        }
        grid_sync();
        combine_gru(g_pgi0, g_pgh0, b_ih0, b_hh0, g_h0f[r], g_h0f[w], g_h0s[w]);
        grid_sync();

        {   // layer 1 gates
            MG gi = { g_h0s[w], (long)BH, g_wih1s, (long)G3H * HH,
                      1024, 32, 2, 3, 24, G3H, g_pgi1 };
            MG gh = { g_h1s[r], (long)BH, g_whh1s, (long)G3H * HH,
                      1024, 32, 2, 3, 24, G3H, g_pgh1 };
            run_units(gi, &gh, sA, sW);
        }
        grid_sync();
        combine_gru(g_pgi1, g_pgh1, b_ih1, b_hh1, g_h1f[r], g_h1f[w], g_h1s[w]);
        grid_sync();

        {   // output logits partials
            MG s = { g_h1s[w], (long)BH, g_wouts, (long)VV * HH,
                     1024, 32, 1, 6, 8, VV, g_pout };
            run_units(s, nullptr, sA, sW);
        }
        grid_sync();

        argmax_phase(b_out, out, emb, samples, t, sv, si);
        grid_sync();
    }
}

extern "C" void kernel_launch(void* const* d_in, const int* in_sizes, int n_in,
                              void* d_out, int out_size) {
    const float* z     = (const float*)d_in[0];
    const float* emb   = (const float*)d_in[3];
    const float* x0    = (const float*)d_in[4];
    const float* w_z1  = (const float*)d_in[5];
    const float* b_z1  = (const float*)d_in[6];
    const float* w_z2  = (const float*)d_in[7];
    const float* b_z2  = (const float*)d_in[8];
    const float* w_ih0 = (const float*)d_in[9];
    const float* w_hh0 = (const float*)d_in[10];
    const float* b_ih0 = (const float*)d_in[11];
    const float* b_hh0 = (const float*)d_in[12];
    const float* w_ih1 = (const float*)d_in[13];
    const float* w_hh1 = (const float*)d_in[14];
    const float* b_ih1 = (const float*)d_in[15];
    const float* b_hh1 = (const float*)d_in[16];
    const float* w_out = (const float*)d_in[17];
    const float* b_out = (const float*)d_in[18];
    float* out = (float*)d_out;

    const long BTV = (long)BB * TT * VV;
    float* samples_base = ((long)out_size >= BTV + (long)BB * TT) ? (out + BTV) : nullptr;

    srdec<<<NBLK, 256>>>(
        z, emb, x0, w_z1, b_z1, w_z2, b_z2,
        w_ih0, w_hh0, b_ih0, b_hh0, w_ih1, w_hh1, b_ih1, b_hh1,
        w_out, b_out, out, samples_base);
}

// round 11
// speedup vs baseline: 3.8017x; 2.2669x over previous
#include <cuda_runtime.h>
#include <cuda_fp16.h>
#include <math.h>
#include <stdint.h>

#define BB 256
#define TT 256
#define HH 1024
#define VV 1024
#define G3H 3072
#define NBLK 148
#define BH (BB * HH)
#define DYN_SMEM 81920

// ---------------- persistent device state ----------------
__device__ float g_h0f[2][BH];
__device__ float g_h1f[2][BH];
__device__ float g_pgi0[3L * BB * G3H];
__device__ float g_pgh0[3L * BB * G3H];
__device__ float g_pgi1[3L * BB * G3H];
__device__ float g_pgh1[3L * BB * G3H];
__device__ float g_pout[6L * BB * VV];

__device__ __align__(16) __half g_zs[2L * BB * 256];
__device__ __align__(16) __half g_zhs[2L * BH];
__device__ __align__(16) __half g_xcats[2L * BB * 512];
__device__ __align__(16) __half g_h0s[2][2L * BH];
__device__ __align__(16) __half g_h1s[2][2L * BH];
__device__ __align__(16) __half g_wz1s[2L * HH * 256];
__device__ __align__(16) __half g_wz2s[2L * 256 * HH];
__device__ __align__(16) __half g_wih0s[2L * G3H * 512];
__device__ __align__(16) __half g_whh0s[2L * G3H * HH];
__device__ __align__(16) __half g_wih1s[2L * G3H * HH];
__device__ __align__(16) __half g_whh1s[2L * G3H * HH];
__device__ __align__(16) __half g_wouts[2L * VV * HH];

// ---------------- launch-invariant grid barrier (proven R3) ----------------
__device__ unsigned g_count = 0;
__device__ unsigned g_gen = 0;

__device__ __forceinline__ void grid_sync() {
    __syncthreads();
    if (threadIdx.x == 0) {
        __threadfence();
        const unsigned snap = atomicAdd(&g_gen, 0u);
        const unsigned my = atomicAdd(&g_count, 1u);
        if (my == (unsigned)(gridDim.x - 1)) {
            atomicExch(&g_count, 0u);
            __threadfence();
            atomicAdd(&g_gen, 1u);
        } else {
            while (atomicAdd(&g_gen, 0u) == snap) { __nanosleep(64); }
        }
        __threadfence();
    }
    __syncthreads();
}

// ---------------- helpers ----------------
__device__ __forceinline__ uint32_t smem_u32(const void* p) {
    uint32_t a;
    asm("{ .reg .u64 t; cvta.to.shared.u64 t, %1; cvt.u32.u64 %0, t; }" : "=r"(a) : "l"(p));
    return a;
}
__device__ __forceinline__ void cpa16(uint32_t s, const void* g) {
    asm volatile("cp.async.cg.shared.global [%0], [%1], 16;" :: "r"(s), "l"(g));
}
#define CPA_COMMIT() asm volatile("cp.async.commit_group;" ::: "memory")
#define CPA_WAIT1()  asm volatile("cp.async.wait_group 1;" ::: "memory")

__device__ __forceinline__ void ldm4(uint32_t* r, uint32_t a) {
    asm volatile("ldmatrix.sync.aligned.m8n8.x4.shared.b16 {%0,%1,%2,%3}, [%4];"
                 : "=r"(r[0]), "=r"(r[1]), "=r"(r[2]), "=r"(r[3]) : "r"(a));
}
__device__ __forceinline__ void mma16816(float* c, const uint32_t* a, const uint32_t* b) {
    asm volatile(
        "mma.sync.aligned.m16n8k16.row.col.f32.f16.f16.f32 "
        "{%0,%1,%2,%3}, {%4,%5,%6,%7}, {%8,%9}, {%0,%1,%2,%3};"
        : "+f"(c[0]), "+f"(c[1]), "+f"(c[2]), "+f"(c[3])
        : "r"(a[0]), "r"(a[1]), "r"(a[2]), "r"(a[3]), "r"(b[0]), "r"(b[1]));
}

__device__ __forceinline__ float sigmoidf_(float x) { return 1.0f / (1.0f + expf(-x)); }
__device__ __forceinline__ float seluf_(float x) {
    const float sc = 1.0507009873554805f, al = 1.6732632423543772f;
    return x > 0.f ? sc * x : sc * al * expm1f(x);
}
__device__ __forceinline__ void split2(float a, __half& o0, __half& o1) {
    o0 = __float2half_rn(a);
    o1 = __float2half_rn(a - __half2float(o0));
}

// ---------------- HMMA unit: 128x128 tile, one (term, k-seg) slice ----------------
// terms: 0 -> a0*b0, 1 -> a0*b1, 2 -> a1*b0
struct MG {
    const __half* A; long aps;
    const __half* W; long wps;
    int K; int k32; int kSplit; int nSlices; int nTilesN; int N;
    float* P;
};

__device__ __forceinline__ void issue_stage(const __half* Ab, const __half* Wb, long K,
                                            int m0, int n0, int kidx, int stage,
                                            uint32_t sA, uint32_t sW, int row, int seg) {
    const __half* Ap = Ab + (long)(m0 + row) * K + kidx * 32 + seg * 16;
    const __half* Wp = Wb + (long)(n0 + row) * K + kidx * 32 + seg * 16;
    const uint32_t as = sA + stage * 10240 + row * 80 + seg * 32;
    const uint32_t ws = sW + stage * 10240 + row * 80 + seg * 32;
    cpa16(as, Ap); cpa16(as + 16, Ap + 8);
    cpa16(ws, Wp); cpa16(ws + 16, Wp + 8);
}

__device__ void mma_unit(const MG& g, int m0, int n0, int slice, uint32_t sA, uint32_t sW) {
    const int tid = threadIdx.x, lane = tid & 31, wid = tid >> 5;
    const int wm = wid >> 2, wn = wid & 3;
    const int term = slice % 3;
    const __half* Ab = g.A + (long)(term == 2 ? 1 : 0) * g.aps;
    const __half* Wb = g.W + (long)(term == 1 ? 1 : 0) * g.wps;
    const int nk = g.k32 / g.kSplit;
    const int k0 = (slice / 3) * nk;

    float acc[4][4][4];
#pragma unroll
    for (int i = 0; i < 4; i++)
#pragma unroll
        for (int j = 0; j < 4; j++)
#pragma unroll
            for (int c = 0; c < 4; c++) acc[i][j][c] = 0.f;

    const int row = tid >> 1;
    const int seg = tid & 1;
    const uint32_t aoff =
        (uint32_t)(wm * 64 + ((lane >> 3) & 1) * 8 + (lane & 7)) * 80 + ((lane >> 4) << 4);
    const uint32_t woff =
        (uint32_t)(wn * 32 + ((lane >> 4) << 3) + (lane & 7)) * 80 + (((lane >> 3) & 1) << 4);

    // prologue: stages 0,1
    issue_stage(Ab, Wb, g.K, m0, n0, k0 + 0, 0, sA, sW, row, seg); CPA_COMMIT();
    issue_stage(Ab, Wb, g.K, m0, n0, k0 + 1, 1, sA, sW, row, seg); CPA_COMMIT();

    for (int it = 0; it < nk; it++) {
        CPA_WAIT1();
        __syncthreads();
        if (it + 2 < nk)
            issue_stage(Ab, Wb, g.K, m0, n0, k0 + it + 2, (it + 2) & 3, sA, sW, row, seg);
        CPA_COMMIT();
        const uint32_t ab = sA + (it & 3) * 10240 + aoff;
        const uint32_t wb = sW + (it & 3) * 10240 + woff;
#pragma unroll
        for (int s = 0; s < 2; s++) {
            uint32_t af[4][4], b0[4], b1[4];
#pragma unroll
            for (int mt = 0; mt < 4; mt++) ldm4(af[mt], ab + mt * (16 * 80) + s * 32);
            ldm4(b0, wb + s * 32);
            ldm4(b1, wb + 16 * 80 + s * 32);
#pragma unroll
            for (int mt = 0; mt < 4; mt++) {
                mma16816(acc[mt][0], af[mt], b0);
                mma16816(acc[mt][1], af[mt], b0 + 2);
                mma16816(acc[mt][2], af[mt], b1);
                mma16816(acc[mt][3], af[mt], b1 + 2);
            }
        }
    }

    float* P = g.P + (long)slice * BB * g.N;
#pragma unroll
    for (int mt = 0; mt < 4; mt++)
#pragma unroll
        for (int nt = 0; nt < 4; nt++) {
            const int m = m0 + wm * 64 + mt * 16 + (lane >> 2);
            const int n = n0 + wn * 32 + nt * 8 + (lane & 3) * 2;
            *(float2*)(P + (long)m * g.N + n) = make_float2(acc[mt][nt][0], acc[mt][nt][1]);
            *(float2*)(P + (long)(m + 8) * g.N + n) = make_float2(acc[mt][nt][2], acc[mt][nt][3]);
        }
    __syncthreads();
}

__device__ void run_units(const MG& ga, const MG* gb, uint32_t sA, uint32_t sW) {
    const int na = 2 * ga.nTilesN * ga.nSlices;
    const int nb = gb ? 2 * gb->nTilesN * gb->nSlices : 0;
    for (int u = blockIdx.x; u < na + nb; u += gridDim.x) {
        const MG& g = (u < na) ? ga : *gb;
        const int v = (u < na) ? u : u - na;
        const int slice = v % g.nSlices;
        const int tile = v / g.nSlices;
        mma_unit(g, (tile / g.nTilesN) * 128, (tile % g.nTilesN) * 128, slice, sA, sW);
    }
}

// ---------------- elementwise phases ----------------
__device__ void split_mat(const float* w, __half* d, long n) {
    const long st = (long)gridDim.x * blockDim.x;
    for (long i = (long)blockIdx.x * blockDim.x + threadIdx.x; i < n; i += st) {
        __half s0, s1; split2(w[i], s0, s1);
        d[i] = s0; d[n + i] = s1;
    }
}

__device__ void combine_gru(const float* pgi, const float* pgh,
                            const float* bih, const float* bhh,
                            const float* hp, float* hn, __half* hs) {
    const long S = (long)BB * G3H;
    for (int i = blockIdx.x * blockDim.x + threadIdx.x; i < BH; i += gridDim.x * blockDim.x) {
        const int b = i >> 10, j = i & 1023;
        const long r0 = (long)b * G3H + j, z0 = r0 + HH, n0 = r0 + 2 * HH;
        const float gir = pgi[r0] + pgi[S + r0] + pgi[2 * S + r0] + bih[j];
        const float giz = pgi[z0] + pgi[S + z0] + pgi[2 * S + z0] + bih[HH + j];
        const float gin = pgi[n0] + pgi[S + n0] + pgi[2 * S + n0] + bih[2 * HH + j];
        const float ghr = pgh[r0] + pgh[S + r0] + pgh[2 * S + r0] + bhh[j];
        const float ghz = pgh[z0] + pgh[S + z0] + pgh[2 * S + z0] + bhh[HH + j];
        const float ghn = pgh[n0] + pgh[S + n0] + pgh[2 * S + n0] + bhh[2 * HH + j];
        const float r = sigmoidf_(gir + ghr);
        const float zg = sigmoidf_(giz + ghz);
        const float n = tanhf(gin + r * ghn);
        const float v = (1.0f - zg) * n + zg * hp[i];
        hn[i] = v;
        __half s0, s1; split2(v, s0, s1);
        hs[i] = s0; hs[BH + i] = s1;
    }
}

__device__ void argmax_phase(const float* bout, float* out, const float* emb,
                             float* samples, int t, float* sv, int* si) {
    const long S = (long)BB * VV;
    const int tid = threadIdx.x;
    for (int b = blockIdx.x; b < BB; b += gridDim.x) {
        const float* pb = g_pout + (long)b * VV;
        float* orow = out + (long)b * TT * VV + (long)t * VV;
        float best = -1e30f; int bidx = VV;
        for (int j = tid; j < VV; j += 256) {
            float v = pb[j] + pb[S + j] + pb[2 * S + j] + pb[3 * S + j] +
                      pb[4 * S + j] + pb[5 * S + j] + bout[j];
            v = fmaxf(v, 0.f);
            orow[j] = v;
            if (v > best) { best = v; bidx = j; }
        }
        sv[tid] = best; si[tid] = bidx;
        __syncthreads();
        for (int s = 128; s > 0; s >>= 1) {
            if (tid < s) {
                const float v2 = sv[tid + s]; const int i2 = si[tid + s];
                if (v2 > sv[tid] || (v2 == sv[tid] && i2 < si[tid])) { sv[tid] = v2; si[tid] = i2; }
            }
            __syncthreads();
        }
        const int idx = si[0];
        __syncthreads();
        for (int jj = tid; jj < 256; jj += 256) {
            __half s0, s1;
            split2(emb[(long)idx * 256 + jj], s0, s1);
            __half* xc = g_xcats + (long)b * 512 + jj;
            xc[0] = s0; xc[131072] = s1;
        }
        if (tid == 0 && samples) samples[(long)b * TT + t] = (float)idx;
        __syncthreads();
    }
}

// ---------------- the whole decoder, ONE persistent kernel ----------------
__global__ void __launch_bounds__(256, 1) srdec(
    const float* z, const float* emb, const float* x0,
    const float* w_z1, const float* b_z1, const float* w_z2, const float* b_z2,
    const float* w_ih0, const float* w_hh0, const float* b_ih0, const float* b_hh0,
    const float* w_ih1, const float* w_hh1, const float* b_ih1, const float* b_hh1,
    const float* w_out, const float* b_out, float* out, float* samples) {

    extern __shared__ __align__(16) uint8_t dyn[];
    __shared__ float sv[256];
    __shared__ int si[256];
    const uint32_t sA = smem_u32(dyn);
    const uint32_t sW = sA + 40960;
    const int tid = threadIdx.x;
    const int gst = gridDim.x * blockDim.x;

    // ---- P1: init state + split weights/z ----
    {
        const __half zh16 = __float2half(0.f);
        for (int i = blockIdx.x * blockDim.x + tid; i < BH; i += gst) {
            g_h0f[0][i] = 0.f; g_h1f[0][i] = 0.f;
            g_h0s[0][i] = zh16; g_h0s[0][BH + i] = zh16;
            g_h1s[0][i] = zh16; g_h1s[0][BH + i] = zh16;
        }
        for (int i = blockIdx.x * blockDim.x + tid; i < BB * 256; i += gst) {
            const int b = i >> 8, k = i & 255;
            __half s0, s1; split2(x0[k], s0, s1);
            __half* xc = g_xcats + (long)b * 512 + k;
            xc[0] = s0; xc[131072] = s1;
        }
        split_mat(z, g_zs, (long)BB * 256);
        split_mat(w_z1, g_wz1s, (long)HH * 256);
        split_mat(w_z2, g_wz2s, (long)256 * HH);
        split_mat(w_ih0, g_wih0s, (long)G3H * 512);
        split_mat(w_hh0, g_whh0s, (long)G3H * HH);
        split_mat(w_ih1, g_wih1s, (long)G3H * HH);
        split_mat(w_hh1, g_whh1s, (long)G3H * HH);
        split_mat(w_out, g_wouts, (long)VV * HH);
    }
    grid_sync();

    // ---- P2: zh_raw = z @ w_z1^T (3 partials) ----
    {
        MG s = { g_zs, (long)BB * 256, g_wz1s, (long)HH * 256,
                 256, 8, 1, 3, 8, 1024, g_pgi0 };
        run_units(s, nullptr, sA, sW);
    }
    grid_sync();
    // ---- P3: zh = selu(sum + b_z1), split ----
    for (int i = blockIdx.x * blockDim.x + tid; i < BH; i += gst) {
        const int j = i & 1023;
        const float v = seluf_(g_pgi0[i] + g_pgi0[BH + i] + g_pgi0[2 * BH + i] + b_z1[j]);
        __half s0, s1; split2(v, s0, s1);
        g_zhs[i] = s0; g_zhs[BH + i] = s1;
    }
    grid_sync();
    // ---- P4: zemb partials ----
    {
        MG s = { g_zhs, (long)BH, g_wz2s, (long)256 * HH,
                 1024, 32, 1, 3, 2, 256, g_pgi0 };
        run_units(s, nullptr, sA, sW);
    }
    grid_sync();
    // ---- P5: zemb combine -> xcat[:,256:512] ----
    for (int i = blockIdx.x * blockDim.x + tid; i < BB * 256; i += gst) {
        const int b = i >> 8, k = i & 255;
        const float v = g_pgi0[i] + g_pgi0[65536 + i] + g_pgi0[131072 + i] + b_z2[k];
        __half s0, s1; split2(v, s0, s1);
        __half* xc = g_xcats + (long)b * 512 + 256 + k;
        xc[0] = s0; xc[131072] = s1;
    }
    grid_sync();

    for (int t = 0; t < TT; t++) {
        const int r = t & 1, w = r ^ 1;

        {   // layer 0 gates
            MG gi = { g_xcats, 131072L, g_wih0s, (long)G3H * 512,
                      512, 16, 1, 3, 24, G3H, g_pgi0 };
            MG gh = { g_h0s[r], (long)BH, g_whh0s, (long)G3H * HH,
                      1024, 32, 1, 3, 24, G3H, g_pgh0 };
            run_units(gi, &gh, sA, sW);
        }
        grid_sync();
        combine_gru(g_pgi0, g_pgh0, b_ih0, b_hh0, g_h0f[r], g_h0f[w], g_h0s[w]);
        grid_sync();

        {   // layer 1 gates
            MG gi = { g_h0s[w], (long)BH, g_wih1s, (long)G3H * HH,
                      1024, 32, 1, 3, 24, G3H, g_pgi1 };
            MG gh = { g_h1s[r], (long)BH, g_whh1s, (long)G3H * HH,
                      1024, 32, 1, 3, 24, G3H, g_pgh1 };
            run_units(gi, &gh, sA, sW);
        }
        grid_sync();
        combine_gru(g_pgi1, g_pgh1, b_ih1, b_hh1, g_h1f[r], g_h1f[w], g_h1s[w]);
        grid_sync();

        {   // output logits partials: 6 slices = 3 terms x 2 K-halves
            MG s = { g_h1s[w], (long)BH, g_wouts, (long)VV * HH,
                     1024, 32, 2, 6, 8, VV, g_pout };
            run_units(s, nullptr, sA, sW);
        }
        grid_sync();

        argmax_phase(b_out, out, emb, samples, t, sv, si);
        grid_sync();
    }
}

extern "C" void kernel_launch(void* const* d_in, const int* in_sizes, int n_in,
                              void* d_out, int out_size) {
    const float* z     = (const float*)d_in[0];
    const float* emb   = (const float*)d_in[3];
    const float* x0    = (const float*)d_in[4];
    const float* w_z1  = (const float*)d_in[5];
    const float* b_z1  = (const float*)d_in[6];
    const float* w_z2  = (const float*)d_in[7];
    const float* b_z2  = (const float*)d_in[8];
    const float* w_ih0 = (const float*)d_in[9];
    const float* w_hh0 = (const float*)d_in[10];
    const float* b_ih0 = (const float*)d_in[11];
    const float* b_hh0 = (const float*)d_in[12];
    const float* w_ih1 = (const float*)d_in[13];
    const float* w_hh1 = (const float*)d_in[14];
    const float* b_ih1 = (const float*)d_in[15];
    const float* b_hh1 = (const float*)d_in[16];
    const float* w_out = (const float*)d_in[17];
    const float* b_out = (const float*)d_in[18];
    float* out = (float*)d_out;

    const long BTV = (long)BB * TT * VV;
    float* samples_base = ((long)out_size >= BTV + (long)BB * TT) ? (out + BTV) : nullptr;

    cudaFuncSetAttribute(srdec, cudaFuncAttributeMaxDynamicSharedMemorySize, DYN_SMEM);
    srdec<<<NBLK, 256, DYN_SMEM>>>(
        z, emb, x0, w_z1, b_z1, w_z2, b_z2,
        w_ih0, w_hh0, b_ih0, b_hh0, w_ih1, w_hh1, b_ih1, b_hh1,
        w_out, b_out, out, samples_base);
}

// round 14
// speedup vs baseline: 4.2996x; 1.1310x over previous
#include <cuda_runtime.h>
#include <cuda_fp16.h>
#include <math.h>
#include <stdint.h>

#define BB 256
#define TT 256
#define HH 1024
#define VV 1024
#define G3H 3072
#define NBLK 148
#define NTHR 512
#define BH (BB * HH)
#define DYN_SMEM 81920

// ---------------- persistent device state ----------------
__device__ float g_h0f[2][BH];
__device__ float g_h1f[2][BH];
__device__ float g_pgi0[3L * BB * G3H];
__device__ float g_pgh0[3L * BB * G3H];
__device__ float g_pgi1[3L * BB * G3H];
__device__ float g_pgh1[3L * BB * G3H];
__device__ float g_pout[6L * BB * VV];

__device__ __align__(16) __half g_zs[2L * BB * 256];
__device__ __align__(16) __half g_zhs[2L * BH];
__device__ __align__(16) __half g_xcats[2L * BB * 512];
__device__ __align__(16) __half g_h0s[2][2L * BH];
__device__ __align__(16) __half g_h1s[2][2L * BH];
__device__ __align__(16) __half g_wz1s[2L * HH * 256];
__device__ __align__(16) __half g_wz2s[2L * 256 * HH];
__device__ __align__(16) __half g_wih0s[2L * G3H * 512];
__device__ __align__(16) __half g_whh0s[2L * G3H * HH];
__device__ __align__(16) __half g_wih1s[2L * G3H * HH];
__device__ __align__(16) __half g_whh1s[2L * G3H * HH];
__device__ __align__(16) __half g_wouts[2L * VV * HH];

// ---------------- launch-invariant grid barrier (proven R3) ----------------
__device__ unsigned g_count = 0;
__device__ unsigned g_gen = 0;

__device__ __forceinline__ void grid_sync() {
    __syncthreads();
    if (threadIdx.x == 0) {
        __threadfence();
        const unsigned snap = atomicAdd(&g_gen, 0u);
        const unsigned my = atomicAdd(&g_count, 1u);
        if (my == (unsigned)(gridDim.x - 1)) {
            atomicExch(&g_count, 0u);
            __threadfence();
            atomicAdd(&g_gen, 1u);
        } else {
            while (atomicAdd(&g_gen, 0u) == snap) { __nanosleep(64); }
        }
        __threadfence();
    }
    __syncthreads();
}

// ---------------- helpers ----------------
__device__ __forceinline__ uint32_t smem_u32(const void* p) {
    uint32_t a;
    asm("{ .reg .u64 t; cvta.to.shared.u64 t, %1; cvt.u32.u64 %0, t; }" : "=r"(a) : "l"(p));
    return a;
}
__device__ __forceinline__ void cpa16(uint32_t s, const void* g) {
    asm volatile("cp.async.cg.shared.global [%0], [%1], 16;" :: "r"(s), "l"(g));
}
#define CPA_COMMIT() asm volatile("cp.async.commit_group;" ::: "memory")
#define CPA_WAIT1()  asm volatile("cp.async.wait_group 1;" ::: "memory")

__device__ __forceinline__ void ldm4(uint32_t* r, uint32_t a) {
    asm volatile("ldmatrix.sync.aligned.m8n8.x4.shared.b16 {%0,%1,%2,%3}, [%4];"
                 : "=r"(r[0]), "=r"(r[1]), "=r"(r[2]), "=r"(r[3]) : "r"(a));
}
__device__ __forceinline__ void mma16816(float* c, const uint32_t* a, const uint32_t* b) {
    asm volatile(
        "mma.sync.aligned.m16n8k16.row.col.f32.f16.f16.f32 "
        "{%0,%1,%2,%3}, {%4,%5,%6,%7}, {%8,%9}, {%0,%1,%2,%3};"
        : "+f"(c[0]), "+f"(c[1]), "+f"(c[2]), "+f"(c[3])
        : "r"(a[0]), "r"(a[1]), "r"(a[2]), "r"(a[3]), "r"(b[0]), "r"(b[1]));
}

__device__ __forceinline__ float sigmoidf_(float x) { return 1.0f / (1.0f + expf(-x)); }
__device__ __forceinline__ float seluf_(float x) {
    const float sc = 1.0507009873554805f, al = 1.6732632423543772f;
    return x > 0.f ? sc * x : sc * al * expm1f(x);
}
__device__ __forceinline__ void split2(float a, __half& o0, __half& o1) {
    o0 = __float2half_rn(a);
    o1 = __float2half_rn(a - __half2float(o0));
}

// ---------------- HMMA unit: 128x128 tile, one (term, k-seg) slice ----------------
// terms: 0 -> a0*b0, 1 -> a0*b1, 2 -> a1*b0
struct MG {
    const __half* A; long aps;
    const __half* W; long wps;
    int K; int k32; int kSplit; int nSlices; int nTilesN; int N;
    float* P;
};

// 512 threads: each thread copies one 16B chunk of A and one of W per stage.
__device__ __forceinline__ void issue_stage(const __half* Ab, const __half* Wb, long K,
                                            int m0, int n0, int kidx, int stage,
                                            uint32_t sA, uint32_t sW, int row, int seg) {
    const __half* Ap = Ab + (long)(m0 + row) * K + kidx * 32 + seg * 8;
    const __half* Wp = Wb + (long)(n0 + row) * K + kidx * 32 + seg * 8;
    cpa16(sA + stage * 10240 + row * 80 + seg * 16, Ap);
    cpa16(sW + stage * 10240 + row * 80 + seg * 16, Wp);
}

__device__ void mma_unit(const MG& g, int m0, int n0, int slice, uint32_t sA, uint32_t sW) {
    const int tid = threadIdx.x, lane = tid & 31, wid = tid >> 5;
    const int wm = wid >> 2, wn = wid & 3;                 // 4x4 warp grid, 32x32 tiles
    const int term = slice % 3;
    const __half* Ab = g.A + (long)(term == 2 ? 1 : 0) * g.aps;
    const __half* Wb = g.W + (long)(term == 1 ? 1 : 0) * g.wps;
    const int nk = g.k32 / g.kSplit;
    const int k0 = (slice / 3) * nk;

    float acc[2][4][4];
#pragma unroll
    for (int i = 0; i < 2; i++)
#pragma unroll
        for (int j = 0; j < 4; j++)
#pragma unroll
            for (int c = 0; c < 4; c++) acc[i][j][c] = 0.f;

    const int row = tid >> 2;                               // 0..127
    const int seg = tid & 3;                                // 0..3 (16B chunks)
    const uint32_t aoff =
        (uint32_t)(wm * 32 + ((lane >> 3) & 1) * 8 + (lane & 7)) * 80 + ((lane >> 4) << 4);
    const uint32_t woff =
        (uint32_t)(wn * 32 + ((lane >> 4) << 3) + (lane & 7)) * 80 + (((lane >> 3) & 1) << 4);

    issue_stage(Ab, Wb, g.K, m0, n0, k0 + 0, 0, sA, sW, row, seg); CPA_COMMIT();
    issue_stage(Ab, Wb, g.K, m0, n0, k0 + 1, 1, sA, sW, row, seg); CPA_COMMIT();

    for (int it = 0; it < nk; it++) {
        CPA_WAIT1();
        __syncthreads();
        if (it + 2 < nk)
            issue_stage(Ab, Wb, g.K, m0, n0, k0 + it + 2, (it + 2) & 3, sA, sW, row, seg);
        CPA_COMMIT();
        const uint32_t ab = sA + (it & 3) * 10240 + aoff;
        const uint32_t wb = sW + (it & 3) * 10240 + woff;
#pragma unroll
        for (int s = 0; s < 2; s++) {
            uint32_t af[2][4], b0[4], b1[4];
            ldm4(af[0], ab + s * 32);
            ldm4(af[1], ab + 16 * 80 + s * 32);
            ldm4(b0, wb + s * 32);
            ldm4(b1, wb + 16 * 80 + s * 32);
#pragma unroll
            for (int mt = 0; mt < 2; mt++) {
                mma16816(acc[mt][0], af[mt], b0);
                mma16816(acc[mt][1], af[mt], b0 + 2);
                mma16816(acc[mt][2], af[mt], b1);
                mma16816(acc[mt][3], af[mt], b1 + 2);
            }
        }
    }

    float* P = g.P + (long)slice * BB * g.N;
#pragma unroll
    for (int mt = 0; mt < 2; mt++)
#pragma unroll
        for (int nt = 0; nt < 4; nt++) {
            const int m = m0 + wm * 32 + mt * 16 + (lane >> 2);
            const int n = n0 + wn * 32 + nt * 8 + (lane & 3) * 2;
            *(float2*)(P + (long)m * g.N + n) = make_float2(acc[mt][nt][0], acc[mt][nt][1]);
            *(float2*)(P + (long)(m + 8) * g.N + n) = make_float2(acc[mt][nt][2], acc[mt][nt][3]);
        }
    __syncthreads();
}

__device__ void run_units(const MG& ga, const MG* gb, uint32_t sA, uint32_t sW) {
    const int na = 2 * ga.nTilesN * ga.nSlices;
    const int nb = gb ? 2 * gb->nTilesN * gb->nSlices : 0;
    for (int u = blockIdx.x; u < na + nb; u += gridDim.x) {
        const MG& g = (u < na) ? ga : *gb;
        const int v = (u < na) ? u : u - na;
        const int slice = v % g.nSlices;
        const int tile = v / g.nSlices;
        mma_unit(g, (tile / g.nTilesN) * 128, (tile % g.nTilesN) * 128, slice, sA, sW);
    }
}

// ---------------- elementwise phases ----------------
__device__ void split_mat(const float* w, __half* d, long n) {
    const long st = (long)gridDim.x * blockDim.x;
    for (long i = (long)blockIdx.x * blockDim.x + threadIdx.x; i < n; i += st) {
        __half s0, s1; split2(w[i], s0, s1);
        d[i] = s0; d[n + i] = s1;
    }
}

__device__ void combine_gru(const float* pgi, const float* pgh,
                            const float* bih, const float* bhh,
                            const float* hp, float* hn, __half* hs) {
    const long S = (long)BB * G3H;
    for (int i = blockIdx.x * blockDim.x + threadIdx.x; i < BH; i += gridDim.x * blockDim.x) {
        const int b = i >> 10, j = i & 1023;
        const long r0 = (long)b * G3H + j, z0 = r0 + HH, n0 = r0 + 2 * HH;
        const float gir = pgi[r0] + pgi[S + r0] + pgi[2 * S + r0] + bih[j];
        const float giz = pgi[z0] + pgi[S + z0] + pgi[2 * S + z0] + bih[HH + j];
        const float gin = pgi[n0] + pgi[S + n0] + pgi[2 * S + n0] + bih[2 * HH + j];
        const float ghr = pgh[r0] + pgh[S + r0] + pgh[2 * S + r0] + bhh[j];
        const float ghz = pgh[z0] + pgh[S + z0] + pgh[2 * S + z0] + bhh[HH + j];
        const float ghn = pgh[n0] + pgh[S + n0] + pgh[2 * S + n0] + bhh[2 * HH + j];
        const float r = sigmoidf_(gir + ghr);
        const float zg = sigmoidf_(giz + ghz);
        const float n = tanhf(gin + r * ghn);
        const float v = (1.0f - zg) * n + zg * hp[i];
        hn[i] = v;
        __half s0, s1; split2(v, s0, s1);
        hs[i] = s0; hs[BH + i] = s1;
    }
}

__device__ void argmax_phase(const float* bout, float* out, const float* emb,
                             float* samples, int t, float* sv, int* si) {
    const long S = (long)BB * VV;
    const int tid = threadIdx.x;
    for (int b = blockIdx.x; b < BB; b += gridDim.x) {
        const float* pb = g_pout + (long)b * VV;
        float* orow = out + (long)b * TT * VV + (long)t * VV;
        float best = -1e30f; int bidx = VV;
        for (int j = tid; j < VV; j += NTHR) {
            float v = pb[j] + pb[S + j] + pb[2 * S + j] + pb[3 * S + j] +
                      pb[4 * S + j] + pb[5 * S + j] + bout[j];
            v = fmaxf(v, 0.f);
            orow[j] = v;
            if (v > best) { best = v; bidx = j; }
        }
        sv[tid] = best; si[tid] = bidx;
        __syncthreads();
        for (int s = NTHR / 2; s > 0; s >>= 1) {
            if (tid < s) {
                const float v2 = sv[tid + s]; const int i2 = si[tid + s];
                if (v2 > sv[tid] || (v2 == sv[tid] && i2 < si[tid])) { sv[tid] = v2; si[tid] = i2; }
            }
            __syncthreads();
        }
        const int idx = si[0];
        __syncthreads();
        for (int jj = tid; jj < 256; jj += NTHR) {
            __half s0, s1;
            split2(emb[(long)idx * 256 + jj], s0, s1);
            __half* xc = g_xcats + (long)b * 512 + jj;
            xc[0] = s0; xc[131072] = s1;
        }
        if (tid == 0 && samples) samples[(long)b * TT + t] = (float)idx;
        __syncthreads();
    }
}

// ---------------- the whole decoder, ONE persistent kernel ----------------
__global__ void __launch_bounds__(NTHR, 1) srdec(
    const float* z, const float* emb, const float* x0,
    const float* w_z1, const float* b_z1, const float* w_z2, const float* b_z2,
    const float* w_ih0, const float* w_hh0, const float* b_ih0, const float* b_hh0,
    const float* w_ih1, const float* w_hh1, const float* b_ih1, const float* b_hh1,
    const float* w_out, const float* b_out, float* out, float* samples) {

    extern __shared__ __align__(16) uint8_t dyn[];
    __shared__ float sv[NTHR];
    __shared__ int si[NTHR];
    const uint32_t sA = smem_u32(dyn);
    const uint32_t sW = sA + 40960;
    const int tid = threadIdx.x;
    const int gst = gridDim.x * blockDim.x;

    // ---- P1: init state + split weights/z ----
    {
        const __half zh16 = __float2half(0.f);
        for (int i = blockIdx.x * blockDim.x + tid; i < BH; i += gst) {
            g_h0f[0][i] = 0.f; g_h1f[0][i] = 0.f;
            g_h0s[0][i] = zh16; g_h0s[0][BH + i] = zh16;
            g_h1s[0][i] = zh16; g_h1s[0][BH + i] = zh16;
        }
        for (int i = blockIdx.x * blockDim.x + tid; i < BB * 256; i += gst) {
            const int b = i >> 8, k = i & 255;
            __half s0, s1; split2(x0[k], s0, s1);
            __half* xc = g_xcats + (long)b * 512 + k;
            xc[0] = s0; xc[131072] = s1;
        }
        split_mat(z, g_zs, (long)BB * 256);
        split_mat(w_z1, g_wz1s, (long)HH * 256);
        split_mat(w_z2, g_wz2s, (long)256 * HH);
        split_mat(w_ih0, g_wih0s, (long)G3H * 512);
        split_mat(w_hh0, g_whh0s, (long)G3H * HH);
        split_mat(w_ih1, g_wih1s, (long)G3H * HH);
        split_mat(w_hh1, g_whh1s, (long)G3H * HH);
        split_mat(w_out, g_wouts, (long)VV * HH);
    }
    grid_sync();

    // ---- P2: zh_raw = z @ w_z1^T (3 partials) ----
    {
        MG s = { g_zs, (long)BB * 256, g_wz1s, (long)HH * 256,
                 256, 8, 1, 3, 8, 1024, g_pgi0 };
        run_units(s, nullptr, sA, sW);
    }
    grid_sync();
    // ---- P3: zh = selu(sum + b_z1), split ----
    for (int i = blockIdx.x * blockDim.x + tid; i < BH; i += gst) {
        const int j = i & 1023;
        const float v = seluf_(g_pgi0[i] + g_pgi0[BH + i] + g_pgi0[2 * BH + i] + b_z1[j]);
        __half s0, s1; split2(v, s0, s1);
        g_zhs[i] = s0; g_zhs[BH + i] = s1;
    }
    grid_sync();
    // ---- P4: zemb partials ----
    {
        MG s = { g_zhs, (long)BH, g_wz2s, (long)256 * HH,
                 1024, 32, 1, 3, 2, 256, g_pgi0 };
        run_units(s, nullptr, sA, sW);
    }
    grid_sync();
    // ---- P5: zemb combine -> xcat[:,256:512] ----
    for (int i = blockIdx.x * blockDim.x + tid; i < BB * 256; i += gst) {
        const int b = i >> 8, k = i & 255;
        const float v = g_pgi0[i] + g_pgi0[65536 + i] + g_pgi0[131072 + i] + b_z2[k];
        __half s0, s1; split2(v, s0, s1);
        __half* xc = g_xcats + (long)b * 512 + 256 + k;
        xc[0] = s0; xc[131072] = s1;
    }
    grid_sync();

    for (int t = 0; t < TT; t++) {
        const int r = t & 1, w = r ^ 1;

        {   // layer 0 gates
            MG gi = { g_xcats, 131072L, g_wih0s, (long)G3H * 512,
                      512, 16, 1, 3, 24, G3H, g_pgi0 };
            MG gh = { g_h0s[r], (long)BH, g_whh0s, (long)G3H * HH,
                      1024, 32, 1, 3, 24, G3H, g_pgh0 };
            run_units(gi, &gh, sA, sW);
        }
        grid_sync();
        combine_gru(g_pgi0, g_pgh0, b_ih0, b_hh0, g_h0f[r], g_h0f[w], g_h0s[w]);
        grid_sync();

        {   // layer 1 gates
            MG gi = { g_h0s[w], (long)BH, g_wih1s, (long)G3H * HH,
                      1024, 32, 1, 3, 24, G3H, g_pgi1 };
            MG gh = { g_h1s[r], (long)BH, g_whh1s, (long)G3H * HH,
                      1024, 32, 1, 3, 24, G3H, g_pgh1 };
            run_units(gi, &gh, sA, sW);
        }
        grid_sync();
        combine_gru(g_pgi1, g_pgh1, b_ih1, b_hh1, g_h1f[r], g_h1f[w], g_h1s[w]);
        grid_sync();

        {   // output logits partials: 6 slices = 3 terms x 2 K-halves
            MG s = { g_h1s[w], (long)BH, g_wouts, (long)VV * HH,
                     1024, 32, 2, 6, 8, VV, g_pout };
            run_units(s, nullptr, sA, sW);
        }
        grid_sync();

        argmax_phase(b_out, out, emb, samples, t, sv, si);
        grid_sync();
    }
}

extern "C" void kernel_launch(void* const* d_in, const int* in_sizes, int n_in,
                              void* d_out, int out_size) {
    const float* z     = (const float*)d_in[0];
    const float* emb   = (const float*)d_in[3];
    const float* x0    = (const float*)d_in[4];
    const float* w_z1  = (const float*)d_in[5];
    const float* b_z1  = (const float*)d_in[6];
    const float* w_z2  = (const float*)d_in[7];
    const float* b_z2  = (const float*)d_in[8];
    const float* w_ih0 = (const float*)d_in[9];
    const float* w_hh0 = (const float*)d_in[10];
    const float* b_ih0 = (const float*)d_in[11];
    const float* b_hh0 = (const float*)d_in[12];
    const float* w_ih1 = (const float*)d_in[13];
    const float* w_hh1 = (const float*)d_in[14];
    const float* b_ih1 = (const float*)d_in[15];
    const float* b_hh1 = (const float*)d_in[16];
    const float* w_out = (const float*)d_in[17];
    const float* b_out = (const float*)d_in[18];
    float* out = (float*)d_out;

    const long BTV = (long)BB * TT * VV;
    float* samples_base = ((long)out_size >= BTV + (long)BB * TT) ? (out + BTV) : nullptr;

    cudaFuncSetAttribute(srdec, cudaFuncAttributeMaxDynamicSharedMemorySize, DYN_SMEM);
    srdec<<<NBLK, NTHR, DYN_SMEM>>>(
        z, emb, x0, w_z1, b_z1, w_z2, b_z2,
        w_ih0, w_hh0, b_ih0, b_hh0, w_ih1, w_hh1, b_ih1, b_hh1,
        w_out, b_out, out, samples_base);
}